// round 7
// baseline (speedup 1.0000x reference)
#include <cuda_runtime.h>
#include <cuda_bf16.h>
#include <math.h>

// Problem constants
#define BB 8
#define NN 2048
#define CC 1024
#define KKEEP 1638

// Scratch (allocation-free rule: __device__ globals)
__device__ float g_Q[BB * NN * CC];
__device__ float g_K[BB * NN * CC];
__device__ float g_V[BB * NN * CC];
__device__ float g_S[(size_t)BB * NN * NN];

// smem plane: 8 k-pair rows x (128 + 8 pad) packed-bf16x2 words
#define PADW 136
#define PLANE (8 * PADW)      // 1088 words
#define BUFW (4 * PLANE)      // AH, AL, BH, BL per buffer

// ---------------------------------------------------------------------------
// bf16 split helpers: v = hi + lo + O(2^-18 |v|)
// Packs two k-adjacent values into one .b32 (low 16 = even k).
// ---------------------------------------------------------------------------
__device__ __forceinline__ void split2(float v0, float v1, unsigned& hi, unsigned& lo) {
    __nv_bfloat162 h = __floats2bfloat162_rn(v0, v1);
    float2 hf = __bfloat1622float2(h);
    __nv_bfloat162 l = __floats2bfloat162_rn(v0 - hf.x, v1 - hf.y);
    hi = *reinterpret_cast<unsigned*>(&h);
    lo = *reinterpret_cast<unsigned*>(&l);
}

__device__ __forceinline__ void mma16(float* c, const unsigned* a, const unsigned* b) {
    asm volatile(
        "mma.sync.aligned.m16n8k16.row.col.f32.bf16.bf16.f32 "
        "{%0,%1,%2,%3}, {%4,%5,%6,%7}, {%8,%9}, {%0,%1,%2,%3};"
        : "+f"(c[0]), "+f"(c[1]), "+f"(c[2]), "+f"(c[3])
        : "r"(a[0]), "r"(a[1]), "r"(a[2]), "r"(a[3]), "r"(b[0]), "r"(b[1]));
}

// ---------------------------------------------------------------------------
// fp32-accurate GEMM via 3-term bf16 split on tensor cores.
// 128x128x16 tile, 256 threads, 8 warps (2x4) each owning 64x32.
//   TRANSB: true  -> B is [N,K] row-major (NT), false -> B is [K,N] (NN)
//   BIAS:   add bias[n]
// C[m][n] = scale * sum_k A[m][k]*Bop[k][n] (+ bias[n]); batched over z.
// ---------------------------------------------------------------------------
template <bool TRANSB, bool BIAS>
__global__ void __launch_bounds__(256, 2)
mma_gemm(const float* __restrict__ A, const float* __restrict__ B,
         float* __restrict__ C, const float* __restrict__ bias,
         int M, int N, int K,
         long long sA, long long sB, long long sC, float scale) {
    __shared__ unsigned sm[2 * BUFW];

    A += (size_t)blockIdx.z * sA;
    B += (size_t)blockIdx.z * sB;
    C += (size_t)blockIdx.z * sC;

    const int t = threadIdx.x;
    const int lane = t & 31;
    const int warp = t >> 5;
    const int wm = warp & 1;   // 2 warps along M
    const int wn = warp >> 1;  // 4 warps along N
    const int g = lane >> 2;   // 0..7
    const int tg = lane & 3;   // 0..3

    const int m0 = blockIdx.y * 128;
    const int n0 = blockIdx.x * 128;
    const int aBase = wm * 64;
    const int bBase = wn * 32;

    float acc[4][4][4];
#pragma unroll
    for (int i = 0; i < 4; i++)
#pragma unroll
        for (int j = 0; j < 4; j++)
#pragma unroll
            for (int r = 0; r < 4; r++) acc[i][j][r] = 0.f;

    const int NK = K / 16;
    float4 ra[2], rb[2];

    // --- global load of tile kt into registers ---
    auto load_tile = [&](int kt) {
        const int k0 = kt * 16;
#pragma unroll
        for (int i = 0; i < 2; i++) {
            int idx = t + i * 256;
            int row = idx >> 2, kq = idx & 3;
            ra[i] = *(const float4*)&A[(size_t)(m0 + row) * K + k0 + kq * 4];
        }
        if (TRANSB) {
#pragma unroll
            for (int i = 0; i < 2; i++) {
                int idx = t + i * 256;
                int row = idx >> 2, kq = idx & 3;
                rb[i] = *(const float4*)&B[(size_t)(n0 + row) * K + k0 + kq * 4];
            }
        } else {
            // B [K,N]: thread owns k-pair kp = t>>5, cols n4..n4+3
            int kp = t >> 5, n4 = (t & 31) * 4;
            rb[0] = *(const float4*)&B[(size_t)(k0 + 2 * kp) * N + n0 + n4];
            rb[1] = *(const float4*)&B[(size_t)(k0 + 2 * kp + 1) * N + n0 + n4];
        }
    };

    // --- split to bf16 hi/lo planes in smem buffer buf ---
    auto store_tile = [&](int buf) {
        unsigned* AH = sm + buf * BUFW;
        unsigned* AL = AH + PLANE;
        unsigned* BH = AH + 2 * PLANE;
        unsigned* BL = AH + 3 * PLANE;
#pragma unroll
        for (int i = 0; i < 2; i++) {
            int idx = t + i * 256;
            int row = idx >> 2, kq = idx & 3;
            unsigned h, l;
            split2(ra[i].x, ra[i].y, h, l);
            AH[(kq * 2) * PADW + row] = h;
            AL[(kq * 2) * PADW + row] = l;
            split2(ra[i].z, ra[i].w, h, l);
            AH[(kq * 2 + 1) * PADW + row] = h;
            AL[(kq * 2 + 1) * PADW + row] = l;
        }
        if (TRANSB) {
#pragma unroll
            for (int i = 0; i < 2; i++) {
                int idx = t + i * 256;
                int row = idx >> 2, kq = idx & 3;
                unsigned h, l;
                split2(rb[i].x, rb[i].y, h, l);
                BH[(kq * 2) * PADW + row] = h;
                BL[(kq * 2) * PADW + row] = l;
                split2(rb[i].z, rb[i].w, h, l);
                BH[(kq * 2 + 1) * PADW + row] = h;
                BL[(kq * 2 + 1) * PADW + row] = l;
            }
        } else {
            int kp = t >> 5, n4 = (t & 31) * 4;
            const float f0[4] = {rb[0].x, rb[0].y, rb[0].z, rb[0].w};
            const float f1[4] = {rb[1].x, rb[1].y, rb[1].z, rb[1].w};
            unsigned h[4], l[4];
#pragma unroll
            for (int j = 0; j < 4; j++) split2(f0[j], f1[j], h[j], l[j]);
            *(uint4*)&BH[kp * PADW + n4] = make_uint4(h[0], h[1], h[2], h[3]);
            *(uint4*)&BL[kp * PADW + n4] = make_uint4(l[0], l[1], l[2], l[3]);
        }
    };

    load_tile(0);
    store_tile(0);
    __syncthreads();

    for (int kt = 0; kt < NK; kt++) {
        const int buf = kt & 1;
        if (kt + 1 < NK) load_tile(kt + 1);

        const unsigned* AH = sm + buf * BUFW;
        const unsigned* AL = AH + PLANE;
        const unsigned* BH = AH + 2 * PLANE;
        const unsigned* BL = AH + 3 * PLANE;

        // Phase 1: ah * bh
        unsigned ah[4][4], bh[4][2];
#pragma unroll
        for (int mt = 0; mt < 4; mt++) {
            int mo = aBase + mt * 16 + g;
            ah[mt][0] = AH[tg * PADW + mo];
            ah[mt][1] = AH[tg * PADW + mo + 8];
            ah[mt][2] = AH[(tg + 4) * PADW + mo];
            ah[mt][3] = AH[(tg + 4) * PADW + mo + 8];
        }
#pragma unroll
        for (int nt = 0; nt < 4; nt++) {
            int no = bBase + nt * 8 + g;
            bh[nt][0] = BH[tg * PADW + no];
            bh[nt][1] = BH[(tg + 4) * PADW + no];
        }
#pragma unroll
        for (int mt = 0; mt < 4; mt++)
#pragma unroll
            for (int nt = 0; nt < 4; nt++) mma16(acc[mt][nt], ah[mt], bh[nt]);

        // Phase 2: ah * bl
        {
            unsigned bl[4][2];
#pragma unroll
            for (int nt = 0; nt < 4; nt++) {
                int no = bBase + nt * 8 + g;
                bl[nt][0] = BL[tg * PADW + no];
                bl[nt][1] = BL[(tg + 4) * PADW + no];
            }
#pragma unroll
            for (int mt = 0; mt < 4; mt++)
#pragma unroll
                for (int nt = 0; nt < 4; nt++) mma16(acc[mt][nt], ah[mt], bl[nt]);
        }

        // Phase 3: al * bh
        {
            unsigned al[4][4];
#pragma unroll
            for (int mt = 0; mt < 4; mt++) {
                int mo = aBase + mt * 16 + g;
                al[mt][0] = AL[tg * PADW + mo];
                al[mt][1] = AL[tg * PADW + mo + 8];
                al[mt][2] = AL[(tg + 4) * PADW + mo];
                al[mt][3] = AL[(tg + 4) * PADW + mo + 8];
            }
#pragma unroll
            for (int mt = 0; mt < 4; mt++)
#pragma unroll
                for (int nt = 0; nt < 4; nt++) mma16(acc[mt][nt], al[mt], bh[nt]);
        }

        __syncthreads();
        if (kt + 1 < NK) {
            store_tile((kt + 1) & 1);
            __syncthreads();
        }
    }

    // --- epilogue ---
#pragma unroll
    for (int mt = 0; mt < 4; mt++) {
        int m = m0 + aBase + mt * 16 + g;
#pragma unroll
        for (int nt = 0; nt < 4; nt++) {
            int n = n0 + bBase + nt * 8 + tg * 2;
            float b0 = 0.f, b1 = 0.f;
            if (BIAS) { b0 = bias[n]; b1 = bias[n + 1]; }
            float2 v0 = make_float2(acc[mt][nt][0] * scale + b0,
                                    acc[mt][nt][1] * scale + b1);
            float2 v1 = make_float2(acc[mt][nt][2] * scale + b0,
                                    acc[mt][nt][3] * scale + b1);
            *(float2*)&C[(size_t)m * N + n] = v0;
            *(float2*)&C[(size_t)(m + 8) * N + n] = v1;
        }
    }
}

// ---------------------------------------------------------------------------
// Per-row exact top-k threshold (4-pass MSB radix select) + masked softmax.
// One block (256 threads) per row of 2048. Masked entries -> exactly 0.
// ---------------------------------------------------------------------------
__device__ __forceinline__ unsigned f2u(float f) {
    unsigned b = __float_as_uint(f);
    return (b & 0x80000000u) ? ~b : (b | 0x80000000u);
}
__device__ __forceinline__ float u2f(unsigned u) {
    unsigned b = (u & 0x80000000u) ? (u & 0x7fffffffu) : ~u;
    return __uint_as_float(b);
}

__global__ void __launch_bounds__(256) topk_softmax(float* __restrict__ S) {
    const size_t row = blockIdx.x;
    float* p = S + row * NN;
    const int tid = threadIdx.x;  // 256 threads, 8 elems each

    __shared__ int hist[256];
    __shared__ int s_digit, s_rem;
    __shared__ unsigned s_warpk[8];
    __shared__ float s_warpf[8];
    __shared__ float s_sum;

    unsigned key[8];
    float val[8];
    unsigned lmax = 0;
#pragma unroll
    for (int i = 0; i < 8; i++) {
        float f = p[tid + i * 256];
        val[i] = f;
        key[i] = f2u(f);
        lmax = max(lmax, key[i]);
    }

    lmax = __reduce_max_sync(0xffffffffu, lmax);
    if ((tid & 31) == 0) s_warpk[tid >> 5] = lmax;
    __syncthreads();
    if (tid == 0) {
        unsigned m = s_warpk[0];
#pragma unroll
        for (int w = 1; w < 8; w++) m = max(m, s_warpk[w]);
        s_warpk[0] = m;
        s_rem = KKEEP;
    }

    unsigned prefix = 0, pmask = 0;
    for (int shift = 24; shift >= 0; shift -= 8) {
        hist[tid] = 0;
        __syncthreads();
#pragma unroll
        for (int i = 0; i < 8; i++)
            if ((key[i] & pmask) == prefix)
                atomicAdd(&hist[(key[i] >> shift) & 255], 1);
        __syncthreads();
        if (tid == 0) {
            int remk = s_rem, cum = 0, d = 255;
            for (; d > 0; --d) {
                int c = hist[d];
                if (cum + c >= remk) break;
                cum += c;
            }
            s_digit = d;
            s_rem = remk - cum;
        }
        __syncthreads();
        prefix |= ((unsigned)s_digit) << shift;
        pmask |= 0xFFu << shift;
    }
    const unsigned thr = prefix;
    const float mval = u2f(s_warpk[0]);

    float e[8];
    float lsum = 0.f;
#pragma unroll
    for (int i = 0; i < 8; i++) {
        if (key[i] >= thr) {
            e[i] = __expf(val[i] - mval);
            lsum += e[i];
        } else {
            e[i] = 0.f;
        }
    }
#pragma unroll
    for (int o = 16; o > 0; o >>= 1) lsum += __shfl_down_sync(0xffffffffu, lsum, o);
    if ((tid & 31) == 0) s_warpf[tid >> 5] = lsum;
    __syncthreads();
    if (tid == 0) {
        float s = 0.f;
#pragma unroll
        for (int w = 0; w < 8; w++) s += s_warpf[w];
        s_sum = s;
    }
    __syncthreads();
    const float inv = 1.0f / s_sum;
#pragma unroll
    for (int i = 0; i < 8; i++) p[tid + i * 256] = e[i] * inv;
}

// ---------------------------------------------------------------------------
// Launch
// ---------------------------------------------------------------------------
extern "C" void kernel_launch(void* const* d_in, const int* in_sizes, int n_in,
                              void* d_out, int out_size) {
    const float* x  = (const float*)d_in[0];
    const float* Wq = (const float*)d_in[1];
    const float* bq = (const float*)d_in[2];
    const float* Wk = (const float*)d_in[3];
    const float* bk = (const float*)d_in[4];
    const float* Wv = (const float*)d_in[5];
    const float* bv = (const float*)d_in[6];
    float* out = (float*)d_out;

    float *Q, *K, *V, *S;
    cudaGetSymbolAddress((void**)&Q, g_Q);
    cudaGetSymbolAddress((void**)&K, g_K);
    cudaGetSymbolAddress((void**)&V, g_V);
    cudaGetSymbolAddress((void**)&S, g_S);

    dim3 thr(256);

    // QKV projections: [16384,1024] x [1024,1024]^T + bias
    dim3 gqkv(CC / 128, (BB * NN) / 128, 1);
    mma_gemm<true, true><<<gqkv, thr>>>(x, Wq, Q, bq, BB * NN, CC, CC, 0, 0, 0, 1.0f);
    mma_gemm<true, true><<<gqkv, thr>>>(x, Wk, K, bk, BB * NN, CC, CC, 0, 0, 0, 1.0f);
    mma_gemm<true, true><<<gqkv, thr>>>(x, Wv, V, bv, BB * NN, CC, CC, 0, 0, 0, 1.0f);

    // S = Q K^T / sqrt(C), batched over B
    dim3 gs(NN / 128, NN / 128, BB);
    mma_gemm<true, false><<<gs, thr>>>(Q, K, S, nullptr, NN, NN, CC,
                                       (long long)NN * CC, (long long)NN * CC,
                                       (long long)NN * NN, 0.03125f);

    // exact top-k mask + softmax (in place)
    topk_softmax<<<BB * NN, 256>>>(S);

    // O = P V, batched over B
    dim3 go(CC / 128, NN / 128, BB);
    mma_gemm<false, false><<<go, thr>>>(S, V, out, nullptr, NN, CC, NN,
                                        (long long)NN * NN, (long long)NN * CC,
                                        (long long)NN * CC, 1.0f);
}

// round 8
// speedup vs baseline: 1.1171x; 1.1171x over previous
#include <cuda_runtime.h>
#include <cuda_bf16.h>
#include <math.h>

// Problem constants
#define BB 8
#define NN 2048
#define CC 1024
#define KKEEP 1638

// Scratch (allocation-free rule: __device__ globals)
__device__ float g_Q[BB * NN * CC];
__device__ float g_K[BB * NN * CC];
__device__ float g_V[BB * NN * CC];
__device__ float g_S[(size_t)BB * NN * NN];

// ---------------------------------------------------------------------------
// bf16 split helpers: v = hi + lo + O(2^-18 |v|)
// split2 packs (v0, v1) into one .b32, low half = v0.
// ---------------------------------------------------------------------------
__device__ __forceinline__ void split2(float v0, float v1, unsigned& hi, unsigned& lo) {
    __nv_bfloat162 h = __floats2bfloat162_rn(v0, v1);
    float2 hf = __bfloat1622float2(h);
    __nv_bfloat162 l = __floats2bfloat162_rn(v0 - hf.x, v1 - hf.y);
    hi = *reinterpret_cast<unsigned*>(&h);
    lo = *reinterpret_cast<unsigned*>(&l);
}

__device__ __forceinline__ void mma16(float* c, const unsigned* a, const unsigned* b) {
    asm volatile(
        "mma.sync.aligned.m16n8k16.row.col.f32.bf16.bf16.f32 "
        "{%0,%1,%2,%3}, {%4,%5,%6,%7}, {%8,%9}, {%0,%1,%2,%3};"
        : "+f"(c[0]), "+f"(c[1]), "+f"(c[2]), "+f"(c[3])
        : "r"(a[0]), "r"(a[1]), "r"(a[2]), "r"(a[3]), "r"(b[0]), "r"(b[1]));
}

__device__ __forceinline__ void ldm4(unsigned* r, unsigned addr) {
    asm volatile("ldmatrix.sync.aligned.m8n8.x4.shared.b16 {%0,%1,%2,%3}, [%4];"
                 : "=r"(r[0]), "=r"(r[1]), "=r"(r[2]), "=r"(r[3]) : "r"(addr));
}
__device__ __forceinline__ void ldm4t(unsigned* r, unsigned addr) {
    asm volatile("ldmatrix.sync.aligned.m8n8.x4.trans.shared.b16 {%0,%1,%2,%3}, [%4];"
                 : "=r"(r[0]), "=r"(r[1]), "=r"(r[2]), "=r"(r[3]) : "r"(addr));
}

// ---------------------------------------------------------------------------
// fp32-accurate GEMM via 3-term bf16 split on tensor cores, ldmatrix loads.
// 128x128x16 tile, 256 threads, 8 warps (2x4) each owning 64x32.
//   TRANSB: true  -> B is [N,K] row-major (NT), false -> B is [K,N] (NN)
//   BIAS:   add bias[n]
// C[m][n] = scale * sum_k A[m][k]*Bop[k][n] (+ bias[n]); batched over z.
//
// smem layouts (per buffer):
//   A planes (and NT-B planes): [128 rows][48B pitch] (16 data bf16 + pad)
//     -> ldmatrix rows hit 16B groups 3r mod 8: conflict-free.
//   NN-B planes: [16 k-rows][272B pitch] (128 data bf16 + pad), ldmatrix.trans
//     -> rows hit groups 17r mod 8 = r: conflict-free.
// ---------------------------------------------------------------------------
template <bool TRANSB, bool BIAS>
__global__ void __launch_bounds__(256, 2)
mma_gemm(const float* __restrict__ A, const float* __restrict__ B,
         float* __restrict__ C, const float* __restrict__ bias,
         int M, int N, int K,
         long long sA, long long sB, long long sC, float scale) {
    constexpr int APLANE = 128 * 12;                 // words (48B pitch)
    constexpr int BPLANE = TRANSB ? 128 * 12 : 16 * 68;  // words
    constexpr int BUFW = 2 * APLANE + 2 * BPLANE;
    constexpr int BPITCH = TRANSB ? 768 : 32;        // per-p byte step for ldmatrix
    __shared__ __align__(16) unsigned sm[2 * BUFW];

    A += (size_t)blockIdx.z * sA;
    B += (size_t)blockIdx.z * sB;
    C += (size_t)blockIdx.z * sC;

    const int t = threadIdx.x;
    const int lane = t & 31;
    const int warp = t >> 5;
    const int wm = warp & 1;   // 2 warps along M
    const int wn = warp >> 1;  // 4 warps along N
    const int g = lane >> 2;   // 0..7
    const int tg = lane & 3;   // 0..3

    const int m0 = blockIdx.y * 128;
    const int n0 = blockIdx.x * 128;
    const int aBase = wm * 64;
    const int bBase = wn * 32;

    float acc[4][4][4];
#pragma unroll
    for (int i = 0; i < 4; i++)
#pragma unroll
        for (int j = 0; j < 4; j++)
#pragma unroll
            for (int r = 0; r < 4; r++) acc[i][j][r] = 0.f;

    const int NK = K / 16;
    float4 ra[2], rb[2];

    // --- global load of tile kt into registers ---
    auto load_tile = [&](int kt) {
        const int k0 = kt * 16;
#pragma unroll
        for (int i = 0; i < 2; i++) {
            int idx = t + i * 256;
            int row = idx >> 2, kq = idx & 3;
            ra[i] = *(const float4*)&A[(size_t)(m0 + row) * K + k0 + kq * 4];
        }
        if (TRANSB) {
#pragma unroll
            for (int i = 0; i < 2; i++) {
                int idx = t + i * 256;
                int row = idx >> 2, kq = idx & 3;
                rb[i] = *(const float4*)&B[(size_t)(n0 + row) * K + k0 + kq * 4];
            }
        } else {
            int kp = t >> 5, n4 = (t & 31) * 4;
            rb[0] = *(const float4*)&B[(size_t)(k0 + 2 * kp) * N + n0 + n4];
            rb[1] = *(const float4*)&B[(size_t)(k0 + 2 * kp + 1) * N + n0 + n4];
        }
    };

    // --- split to bf16 hi/lo planes in smem buffer buf ---
    auto store_tile = [&](int buf) {
        unsigned* AH = sm + buf * BUFW;
        unsigned* AL = AH + APLANE;
        unsigned* BH = AH + 2 * APLANE;
        unsigned* BL = BH + BPLANE;
#pragma unroll
        for (int i = 0; i < 2; i++) {
            int idx = t + i * 256;
            int row = idx >> 2, kq = idx & 3;
            unsigned h0, l0, h1, l1;
            split2(ra[i].x, ra[i].y, h0, l0);
            split2(ra[i].z, ra[i].w, h1, l1);
            *(uint2*)&AH[row * 12 + kq * 2] = make_uint2(h0, h1);
            *(uint2*)&AL[row * 12 + kq * 2] = make_uint2(l0, l1);
        }
        if (TRANSB) {
#pragma unroll
            for (int i = 0; i < 2; i++) {
                int idx = t + i * 256;
                int row = idx >> 2, kq = idx & 3;
                unsigned h0, l0, h1, l1;
                split2(rb[i].x, rb[i].y, h0, l0);
                split2(rb[i].z, rb[i].w, h1, l1);
                *(uint2*)&BH[row * 12 + kq * 2] = make_uint2(h0, h1);
                *(uint2*)&BL[row * 12 + kq * 2] = make_uint2(l0, l1);
            }
        } else {
            // [k][n] layout: pack consecutive-n pairs (ldmatrix.trans re-pairs to k)
            int kp = t >> 5, n2 = (t & 31) * 2;
            unsigned h0, l0, h1, l1;
            split2(rb[0].x, rb[0].y, h0, l0);
            split2(rb[0].z, rb[0].w, h1, l1);
            *(uint2*)&BH[(2 * kp) * 68 + n2] = make_uint2(h0, h1);
            *(uint2*)&BL[(2 * kp) * 68 + n2] = make_uint2(l0, l1);
            split2(rb[1].x, rb[1].y, h0, l0);
            split2(rb[1].z, rb[1].w, h1, l1);
            *(uint2*)&BH[(2 * kp + 1) * 68 + n2] = make_uint2(h0, h1);
            *(uint2*)&BL[(2 * kp + 1) * 68 + n2] = make_uint2(l0, l1);
        }
    };

    // --- per-thread ldmatrix base addresses (bytes, shared space) ---
    const unsigned sbase = (unsigned)__cvta_generic_to_shared(sm);
    // A / NT-B: matrices ordered (rows0-7,k0-7),(rows8-15,k0-7),(rows0-7,k8-15),(rows8-15,k8-15)
    const unsigned aAddr =
        sbase + (aBase + (lane & 7) + ((lane >> 3) & 1) * 8) * 48 + (lane >> 4) * 16;
    unsigned bAddr;
    if (TRANSB) {
        // matrices: (n0-7,k0-7),(n0-7,k8-15),(n8-15,k0-7),(n8-15,k8-15)
        bAddr = sbase + 2 * APLANE * 4 +
                (bBase + (lane & 7) + (lane >> 4) * 8) * 48 + ((lane >> 3) & 1) * 16;
    } else {
        // trans: (k0-7,n0-7),(k8-15,n0-7),(k0-7,n8-15),(k8-15,n8-15)
        bAddr = sbase + 2 * APLANE * 4 +
                ((lane & 7) + ((lane >> 3) & 1) * 8) * 272 + bBase * 2 + (lane >> 4) * 16;
    }

    load_tile(0);
    store_tile(0);
    __syncthreads();

    for (int kt = 0; kt < NK; kt++) {
        const unsigned bufB = (unsigned)(kt & 1) * (BUFW * 4);
        if (kt + 1 < NK) load_tile(kt + 1);

        // Phase 1: ah * bh
        unsigned ah[4][4], bh[2][4];
#pragma unroll
        for (int mt = 0; mt < 4; mt++) ldm4(ah[mt], aAddr + bufB + mt * 768);
#pragma unroll
        for (int p = 0; p < 2; p++) {
            if (TRANSB) ldm4(bh[p], bAddr + bufB + p * BPITCH);
            else        ldm4t(bh[p], bAddr + bufB + p * BPITCH);
        }
#pragma unroll
        for (int mt = 0; mt < 4; mt++)
#pragma unroll
            for (int nt = 0; nt < 4; nt++)
                mma16(acc[mt][nt], ah[mt], &bh[nt >> 1][(nt & 1) * 2]);

        // Phase 2: ah * bl
        {
            unsigned bl[2][4];
#pragma unroll
            for (int p = 0; p < 2; p++) {
                if (TRANSB) ldm4(bl[p], bAddr + bufB + BPLANE * 4 + p * BPITCH);
                else        ldm4t(bl[p], bAddr + bufB + BPLANE * 4 + p * BPITCH);
            }
#pragma unroll
            for (int mt = 0; mt < 4; mt++)
#pragma unroll
                for (int nt = 0; nt < 4; nt++)
                    mma16(acc[mt][nt], ah[mt], &bl[nt >> 1][(nt & 1) * 2]);
        }

        // Phase 3: al * bh
        {
            unsigned al[4][4];
#pragma unroll
            for (int mt = 0; mt < 4; mt++) ldm4(al[mt], aAddr + bufB + APLANE * 4 + mt * 768);
#pragma unroll
            for (int mt = 0; mt < 4; mt++)
#pragma unroll
                for (int nt = 0; nt < 4; nt++)
                    mma16(acc[mt][nt], al[mt], &bh[nt >> 1][(nt & 1) * 2]);
        }

        __syncthreads();
        if (kt + 1 < NK) {
            store_tile((kt + 1) & 1);
            __syncthreads();
        }
    }

    // --- epilogue ---
#pragma unroll
    for (int mt = 0; mt < 4; mt++) {
        int m = m0 + aBase + mt * 16 + g;
#pragma unroll
        for (int nt = 0; nt < 4; nt++) {
            int n = n0 + bBase + nt * 8 + tg * 2;
            float b0 = 0.f, b1 = 0.f;
            if (BIAS) { b0 = bias[n]; b1 = bias[n + 1]; }
            float2 v0 = make_float2(acc[mt][nt][0] * scale + b0,
                                    acc[mt][nt][1] * scale + b1);
            float2 v1 = make_float2(acc[mt][nt][2] * scale + b0,
                                    acc[mt][nt][3] * scale + b1);
            *(float2*)&C[(size_t)m * N + n] = v0;
            *(float2*)&C[(size_t)(m + 8) * N + n] = v1;
        }
    }
}

// ---------------------------------------------------------------------------
// Per-row exact top-k threshold (4-pass MSB radix select) + masked softmax.
// One block (256 threads) per row of 2048. Masked entries -> exactly 0.
// ---------------------------------------------------------------------------
__device__ __forceinline__ unsigned f2u(float f) {
    unsigned b = __float_as_uint(f);
    return (b & 0x80000000u) ? ~b : (b | 0x80000000u);
}
__device__ __forceinline__ float u2f(unsigned u) {
    unsigned b = (u & 0x80000000u) ? (u & 0x7fffffffu) : ~u;
    return __uint_as_float(b);
}

__global__ void __launch_bounds__(256) topk_softmax(float* __restrict__ S) {
    const size_t row = blockIdx.x;
    float* p = S + row * NN;
    const int tid = threadIdx.x;  // 256 threads, 8 elems each

    __shared__ int hist[256];
    __shared__ int s_digit, s_rem;
    __shared__ unsigned s_warpk[8];
    __shared__ float s_warpf[8];
    __shared__ float s_sum;

    unsigned key[8];
    float val[8];
    unsigned lmax = 0;
#pragma unroll
    for (int i = 0; i < 8; i++) {
        float f = p[tid + i * 256];
        val[i] = f;
        key[i] = f2u(f);
        lmax = max(lmax, key[i]);
    }

    lmax = __reduce_max_sync(0xffffffffu, lmax);
    if ((tid & 31) == 0) s_warpk[tid >> 5] = lmax;
    __syncthreads();
    if (tid == 0) {
        unsigned m = s_warpk[0];
#pragma unroll
        for (int w = 1; w < 8; w++) m = max(m, s_warpk[w]);
        s_warpk[0] = m;
        s_rem = KKEEP;
    }

    unsigned prefix = 0, pmask = 0;
    for (int shift = 24; shift >= 0; shift -= 8) {
        hist[tid] = 0;
        __syncthreads();
#pragma unroll
        for (int i = 0; i < 8; i++)
            if ((key[i] & pmask) == prefix)
                atomicAdd(&hist[(key[i] >> shift) & 255], 1);
        __syncthreads();
        if (tid == 0) {
            int remk = s_rem, cum = 0, d = 255;
            for (; d > 0; --d) {
                int c = hist[d];
                if (cum + c >= remk) break;
                cum += c;
            }
            s_digit = d;
            s_rem = remk - cum;
        }
        __syncthreads();
        prefix |= ((unsigned)s_digit) << shift;
        pmask |= 0xFFu << shift;
    }
    const unsigned thr = prefix;
    const float mval = u2f(s_warpk[0]);

    float e[8];
    float lsum = 0.f;
#pragma unroll
    for (int i = 0; i < 8; i++) {
        if (key[i] >= thr) {
            e[i] = __expf(val[i] - mval);
            lsum += e[i];
        } else {
            e[i] = 0.f;
        }
    }
#pragma unroll
    for (int o = 16; o > 0; o >>= 1) lsum += __shfl_down_sync(0xffffffffu, lsum, o);
    if ((tid & 31) == 0) s_warpf[tid >> 5] = lsum;
    __syncthreads();
    if (tid == 0) {
        float s = 0.f;
#pragma unroll
        for (int w = 0; w < 8; w++) s += s_warpf[w];
        s_sum = s;
    }
    __syncthreads();
    const float inv = 1.0f / s_sum;
#pragma unroll
    for (int i = 0; i < 8; i++) p[tid + i * 256] = e[i] * inv;
}

// ---------------------------------------------------------------------------
// Launch
// ---------------------------------------------------------------------------
extern "C" void kernel_launch(void* const* d_in, const int* in_sizes, int n_in,
                              void* d_out, int out_size) {
    const float* x  = (const float*)d_in[0];
    const float* Wq = (const float*)d_in[1];
    const float* bq = (const float*)d_in[2];
    const float* Wk = (const float*)d_in[3];
    const float* bk = (const float*)d_in[4];
    const float* Wv = (const float*)d_in[5];
    const float* bv = (const float*)d_in[6];
    float* out = (float*)d_out;

    float *Q, *K, *V, *S;
    cudaGetSymbolAddress((void**)&Q, g_Q);
    cudaGetSymbolAddress((void**)&K, g_K);
    cudaGetSymbolAddress((void**)&V, g_V);
    cudaGetSymbolAddress((void**)&S, g_S);

    dim3 thr(256);

    // QKV projections: [16384,1024] x [1024,1024]^T + bias
    dim3 gqkv(CC / 128, (BB * NN) / 128, 1);
    mma_gemm<true, true><<<gqkv, thr>>>(x, Wq, Q, bq, BB * NN, CC, CC, 0, 0, 0, 1.0f);
    mma_gemm<true, true><<<gqkv, thr>>>(x, Wk, K, bk, BB * NN, CC, CC, 0, 0, 0, 1.0f);
    mma_gemm<true, true><<<gqkv, thr>>>(x, Wv, V, bv, BB * NN, CC, CC, 0, 0, 0, 1.0f);

    // S = Q K^T / sqrt(C), batched over B
    dim3 gs(NN / 128, NN / 128, BB);
    mma_gemm<true, false><<<gs, thr>>>(Q, K, S, nullptr, NN, NN, CC,
                                       (long long)NN * CC, (long long)NN * CC,
                                       (long long)NN * NN, 0.03125f);

    // exact top-k mask + softmax (in place)
    topk_softmax<<<BB * NN, 256>>>(S);

    // O = P V, batched over B
    dim3 go(CC / 128, NN / 128, BB);
    mma_gemm<false, false><<<go, thr>>>(S, V, out, nullptr, NN, CC, NN,
                                        (long long)NN * NN, (long long)NN * CC,
                                        (long long)NN * CC, 1.0f);
}

// round 11
// speedup vs baseline: 1.2594x; 1.1274x over previous
#include <cuda_runtime.h>
#include <cuda_bf16.h>
#include <cstdint>

// Problem constants
#define BB 8
#define NN 2048
#define CC 1024
#define KKEEP 1638

// Scratch (allocation-free rule: __device__ globals) — all operands pre-split bf16
__device__ __nv_bfloat16 g_xh[BB * NN * CC], g_xl[BB * NN * CC];
__device__ __nv_bfloat16 g_Wqh[CC * CC], g_Wql[CC * CC];
__device__ __nv_bfloat16 g_Wkh[CC * CC], g_Wkl[CC * CC];
__device__ __nv_bfloat16 g_Wvh[CC * CC], g_Wvl[CC * CC];
__device__ __nv_bfloat16 g_Qh[BB * NN * CC], g_Ql[BB * NN * CC];
__device__ __nv_bfloat16 g_Kh[BB * NN * CC], g_Kl[BB * NN * CC];
__device__ __nv_bfloat16 g_Vh[BB * NN * CC], g_Vl[BB * NN * CC];
__device__ float g_S[(size_t)BB * NN * NN];
__device__ __nv_bfloat16 g_Ph[(size_t)BB * NN * NN], g_Pl[(size_t)BB * NN * NN];

// ---------------------------------------------------------------------------
// helpers
// ---------------------------------------------------------------------------
__device__ __forceinline__ void split2(float v0, float v1, unsigned& hi, unsigned& lo) {
    __nv_bfloat162 h = __floats2bfloat162_rn(v0, v1);
    float2 hf = __bfloat1622float2(h);
    __nv_bfloat162 l = __floats2bfloat162_rn(v0 - hf.x, v1 - hf.y);
    hi = *reinterpret_cast<unsigned*>(&h);
    lo = *reinterpret_cast<unsigned*>(&l);
}

__device__ __forceinline__ void mma16(float* c, const unsigned* a, const unsigned* b) {
    asm volatile(
        "mma.sync.aligned.m16n8k16.row.col.f32.bf16.bf16.f32 "
        "{%0,%1,%2,%3}, {%4,%5,%6,%7}, {%8,%9}, {%0,%1,%2,%3};"
        : "+f"(c[0]), "+f"(c[1]), "+f"(c[2]), "+f"(c[3])
        : "r"(a[0]), "r"(a[1]), "r"(a[2]), "r"(a[3]), "r"(b[0]), "r"(b[1]));
}
__device__ __forceinline__ void ldm4(unsigned* r, unsigned addr) {
    asm volatile("ldmatrix.sync.aligned.m8n8.x4.shared.b16 {%0,%1,%2,%3}, [%4];"
                 : "=r"(r[0]), "=r"(r[1]), "=r"(r[2]), "=r"(r[3]) : "r"(addr));
}
__device__ __forceinline__ void ldm4t(unsigned* r, unsigned addr) {
    asm volatile("ldmatrix.sync.aligned.m8n8.x4.trans.shared.b16 {%0,%1,%2,%3}, [%4];"
                 : "=r"(r[0]), "=r"(r[1]), "=r"(r[2]), "=r"(r[3]) : "r"(addr));
}
__device__ __forceinline__ void cpa(unsigned s, const void* g) {
    asm volatile("cp.async.cg.shared.global [%0], [%1], 16;" :: "r"(s), "l"(g));
}

// ---------------------------------------------------------------------------
// prep: split fp32 array into bf16 hi/lo planes
// ---------------------------------------------------------------------------
__global__ void split_planes(const float* __restrict__ src,
                             __nv_bfloat16* __restrict__ h,
                             __nv_bfloat16* __restrict__ l, int n4) {
    int i = blockIdx.x * blockDim.x + threadIdx.x;
    if (i < n4) {
        float4 v = ((const float4*)src)[i];
        unsigned h0, l0, h1, l1;
        split2(v.x, v.y, h0, l0);
        split2(v.z, v.w, h1, l1);
        ((uint2*)h)[i] = make_uint2(h0, h1);
        ((uint2*)l)[i] = make_uint2(l0, l1);
    }
}

// ---------------------------------------------------------------------------
// GEMM: all operands pre-split bf16 planes; cp.async 3-stage; ldmatrix + mma.
// CTA tile 128x128, K_tile=32, 256 threads, 8 warps (2x4) each 64x32.
// 3-term split: ah*bh + ah*bl + al*bh (fp32 accum).
//   TRANSB: true -> B planes are [N][K] (NT); false -> [K][N] (NN, ldmatrix.trans)
//   BIAS, SPLITOUT (write hi/lo bf16 planes instead of fp32 C)
// smem stage (32KB): AH(8K) AL(8K) BH(8K) BL(8K)
//   A/NT-B rows: 64B, chunk swizzle c ^ ((r>>1)&3)   (ldmatrix conflict-free)
//   NN-B rows: 256B, chunk swizzle c ^ (r&7)          (ldmatrix.trans conflict-free)
// ---------------------------------------------------------------------------
template <bool TRANSB, bool BIAS, bool SPLITOUT>
__global__ void __launch_bounds__(256, 2)
tc_gemm(const __nv_bfloat16* __restrict__ Ah, const __nv_bfloat16* __restrict__ Al,
        const __nv_bfloat16* __restrict__ Bh, const __nv_bfloat16* __restrict__ Bl,
        float* __restrict__ C, __nv_bfloat16* __restrict__ Ch,
        __nv_bfloat16* __restrict__ Cl, const float* __restrict__ bias,
        int Nld, int lda, int ldb, int K,
        long long sA, long long sB, long long sC, float scale) {
    extern __shared__ __align__(16) unsigned char dsm[];
    const unsigned stiles = (unsigned)__cvta_generic_to_shared(dsm);

    Ah += (size_t)blockIdx.z * sA;
    Al += (size_t)blockIdx.z * sA;
    Bh += (size_t)blockIdx.z * sB;
    Bl += (size_t)blockIdx.z * sB;
    if (SPLITOUT) { Ch += (size_t)blockIdx.z * sC; Cl += (size_t)blockIdx.z * sC; }
    else          { C  += (size_t)blockIdx.z * sC; }

    const int t = threadIdx.x;
    const int lane = t & 31;
    const int warp = t >> 5;
    const int wm = warp & 1;
    const int wn = warp >> 1;
    const int g = lane >> 2;
    const int tg = lane & 3;

    const int m0 = blockIdx.y * 128;
    const int n0 = blockIdx.x * 128;
    const int aBase = wm * 64;
    const int bBase = wn * 32;

    float acc[4][4][4];
#pragma unroll
    for (int i = 0; i < 4; i++)
#pragma unroll
        for (int j = 0; j < 4; j++)
#pragma unroll
            for (int r = 0; r < 4; r++) acc[i][j][r] = 0.f;

    const int NK = K / 32;

    // ---- cp.async issue for stage kt (buffer kt%3) ----
    auto load_stage = [&](int kt) {
        if (kt < NK) {
            const unsigned sb = stiles + (unsigned)(kt % 3) * 32768u;
            const int k0 = kt * 32;
#pragma unroll
            for (int p = 0; p < 2; p++) {
                int idx = t + p * 256;
                int r = idx >> 2, c = idx & 3;
                unsigned sa = sb + (unsigned)(r * 64) + (unsigned)((c ^ ((r >> 1) & 3)) << 4);
                size_t go = (size_t)(m0 + r) * lda + k0 + c * 8;
                cpa(sa, Ah + go);
                cpa(sa + 8192u, Al + go);
            }
            if (TRANSB) {
#pragma unroll
                for (int p = 0; p < 2; p++) {
                    int idx = t + p * 256;
                    int r = idx >> 2, c = idx & 3;
                    unsigned sa = sb + 16384u + (unsigned)(r * 64) +
                                  (unsigned)((c ^ ((r >> 1) & 3)) << 4);
                    size_t go = (size_t)(n0 + r) * ldb + k0 + c * 8;
                    cpa(sa, Bh + go);
                    cpa(sa + 8192u, Bl + go);
                }
            } else {
#pragma unroll
                for (int p = 0; p < 2; p++) {
                    int idx = t + p * 256;
                    int r = idx >> 4, c = idx & 15;
                    unsigned sa = sb + 16384u + (unsigned)(r * 256) +
                                  (unsigned)((c ^ (r & 7)) << 4);
                    size_t go = (size_t)(k0 + r) * ldb + n0 + c * 8;
                    cpa(sa, Bh + go);
                    cpa(sa + 8192u, Bl + go);
                }
            }
        }
        asm volatile("cp.async.commit_group;" ::: "memory");
    };

    // ---- per-thread ldmatrix offsets (within stage buffer) ----
    unsigned axk[4][2];
#pragma unroll
    for (int mt = 0; mt < 4; mt++) {
        int ar = aBase + mt * 16 + (lane & 15);
        int rsw = (ar >> 1) & 3;
        int c0 = lane >> 4;
        axk[mt][0] = (unsigned)(ar * 64 + ((c0 ^ rsw) << 4));
        axk[mt][1] = (unsigned)(ar * 64 + (((c0 + 2) ^ rsw) << 4));
    }
    unsigned bxk[2][2];
    if (TRANSB) {
#pragma unroll
        for (int p = 0; p < 2; p++) {
            int br = bBase + p * 16 + (lane & 7) + (lane >> 4) * 8;
            int rsw = (br >> 1) & 3;
            int c0 = (lane >> 3) & 1;
            bxk[p][0] = 16384u + (unsigned)(br * 64 + ((c0 ^ rsw) << 4));
            bxk[p][1] = 16384u + (unsigned)(br * 64 + (((c0 + 2) ^ rsw) << 4));
        }
    } else {
        int kr = (lane & 7) + ((lane >> 3) & 1) * 8;
#pragma unroll
        for (int p = 0; p < 2; p++) {
            int c = bBase / 8 + (lane >> 4) + 2 * p;
            unsigned b0 = 16384u + (unsigned)(kr * 256 + ((c ^ (kr & 7)) << 4));
            bxk[p][0] = b0;
            bxk[p][1] = b0 + 4096u;   // +16 k-rows
        }
    }

    // ---- pipeline ----
    load_stage(0);
    load_stage(1);

    for (int kt = 0; kt < NK; kt++) {
        asm volatile("cp.async.wait_group 1;" ::: "memory");
        __syncthreads();
        const unsigned sb = stiles + (unsigned)(kt % 3) * 32768u;
        load_stage(kt + 2);

#pragma unroll
        for (int ks = 0; ks < 2; ks++) {
            unsigned ah[4][4], bh[2][4];
#pragma unroll
            for (int mt = 0; mt < 4; mt++) ldm4(ah[mt], sb + axk[mt][ks]);
#pragma unroll
            for (int p = 0; p < 2; p++) {
                if (TRANSB) ldm4(bh[p], sb + bxk[p][ks]);
                else        ldm4t(bh[p], sb + bxk[p][ks]);
            }
#pragma unroll
            for (int mt = 0; mt < 4; mt++)
#pragma unroll
                for (int nt = 0; nt < 4; nt++)
                    mma16(acc[mt][nt], ah[mt], &bh[nt >> 1][(nt & 1) * 2]);

            {
                unsigned bl[2][4];
#pragma unroll
                for (int p = 0; p < 2; p++) {
                    if (TRANSB) ldm4(bl[p], sb + bxk[p][ks] + 8192u);
                    else        ldm4t(bl[p], sb + bxk[p][ks] + 8192u);
                }
#pragma unroll
                for (int mt = 0; mt < 4; mt++)
#pragma unroll
                    for (int nt = 0; nt < 4; nt++)
                        mma16(acc[mt][nt], ah[mt], &bl[nt >> 1][(nt & 1) * 2]);
            }
            {
                unsigned al[4][4];
#pragma unroll
                for (int mt = 0; mt < 4; mt++) ldm4(al[mt], sb + axk[mt][ks] + 8192u);
#pragma unroll
                for (int mt = 0; mt < 4; mt++)
#pragma unroll
                    for (int nt = 0; nt < 4; nt++)
                        mma16(acc[mt][nt], al[mt], &bh[nt >> 1][(nt & 1) * 2]);
            }
        }
    }

    // ---- epilogue ----
#pragma unroll
    for (int mt = 0; mt < 4; mt++) {
        int m = m0 + aBase + mt * 16 + g;
#pragma unroll
        for (int nt = 0; nt < 4; nt++) {
            int n = n0 + bBase + nt * 8 + tg * 2;
            float b0 = 0.f, b1 = 0.f;
            if (BIAS) { b0 = bias[n]; b1 = bias[n + 1]; }
            float v00 = acc[mt][nt][0] * scale + b0;
            float v01 = acc[mt][nt][1] * scale + b1;
            float v10 = acc[mt][nt][2] * scale + b0;
            float v11 = acc[mt][nt][3] * scale + b1;
            if (SPLITOUT) {
                unsigned h, l;
                split2(v00, v01, h, l);
                *(unsigned*)&Ch[(size_t)m * Nld + n] = h;
                *(unsigned*)&Cl[(size_t)m * Nld + n] = l;
                split2(v10, v11, h, l);
                *(unsigned*)&Ch[(size_t)(m + 8) * Nld + n] = h;
                *(unsigned*)&Cl[(size_t)(m + 8) * Nld + n] = l;
            } else {
                *(float2*)&C[(size_t)m * Nld + n] = make_float2(v00, v01);
                *(float2*)&C[(size_t)(m + 8) * Nld + n] = make_float2(v10, v11);
            }
        }
    }
}

// ---------------------------------------------------------------------------
// Per-row exact top-k threshold (4-pass MSB radix select) + masked softmax.
// Reads fp32 S; writes P as bf16 hi/lo planes. Masked entries -> exactly 0.
// ---------------------------------------------------------------------------
__device__ __forceinline__ unsigned f2u(float f) {
    unsigned b = __float_as_uint(f);
    return (b & 0x80000000u) ? ~b : (b | 0x80000000u);
}
__device__ __forceinline__ float u2f(unsigned u) {
    unsigned b = (u & 0x80000000u) ? (u & 0x7fffffffu) : ~u;
    return __uint_as_float(b);
}

__global__ void __launch_bounds__(256) topk_softmax(const float* __restrict__ S,
                                                    __nv_bfloat16* __restrict__ Ph,
                                                    __nv_bfloat16* __restrict__ Pl) {
    const size_t row = blockIdx.x;
    const float* p = S + row * NN;
    const int tid = threadIdx.x;

    __shared__ int hist[256];
    __shared__ int s_digit, s_rem;
    __shared__ unsigned s_warpk[8];
    __shared__ float s_warpf[8];
    __shared__ float s_sum;

    unsigned key[8];
    float val[8];
    unsigned lmax = 0;
#pragma unroll
    for (int i = 0; i < 8; i++) {
        float f = p[tid + i * 256];
        val[i] = f;
        key[i] = f2u(f);
        lmax = max(lmax, key[i]);
    }

    lmax = __reduce_max_sync(0xffffffffu, lmax);
    if ((tid & 31) == 0) s_warpk[tid >> 5] = lmax;
    __syncthreads();
    if (tid == 0) {
        unsigned m = s_warpk[0];
#pragma unroll
        for (int w = 1; w < 8; w++) m = max(m, s_warpk[w]);
        s_warpk[0] = m;
        s_rem = KKEEP;
    }

    unsigned prefix = 0, pmask = 0;
    for (int shift = 24; shift >= 0; shift -= 8) {
        hist[tid] = 0;
        __syncthreads();
#pragma unroll
        for (int i = 0; i < 8; i++)
            if ((key[i] & pmask) == prefix)
                atomicAdd(&hist[(key[i] >> shift) & 255], 1);
        __syncthreads();
        if (tid == 0) {
            int remk = s_rem, cum = 0, d = 255;
            for (; d > 0; --d) {
                int c = hist[d];
                if (cum + c >= remk) break;
                cum += c;
            }
            s_digit = d;
            s_rem = remk - cum;
        }
        __syncthreads();
        prefix |= ((unsigned)s_digit) << shift;
        pmask |= 0xFFu << shift;
    }
    const unsigned thr = prefix;
    const float mval = u2f(s_warpk[0]);

    float e[8];
    float lsum = 0.f;
#pragma unroll
    for (int i = 0; i < 8; i++) {
        if (key[i] >= thr) {
            e[i] = __expf(val[i] - mval);
            lsum += e[i];
        } else {
            e[i] = 0.f;
        }
    }
#pragma unroll
    for (int o = 16; o > 0; o >>= 1) lsum += __shfl_down_sync(0xffffffffu, lsum, o);
    if ((tid & 31) == 0) s_warpf[tid >> 5] = lsum;
    __syncthreads();
    if (tid == 0) {
        float s = 0.f;
#pragma unroll
        for (int w = 0; w < 8; w++) s += s_warpf[w];
        s_sum = s;
    }
    __syncthreads();
    const float inv = 1.0f / s_sum;
#pragma unroll
    for (int i = 0; i < 8; i++) {
        float pv = e[i] * inv;
        __nv_bfloat16 h = __float2bfloat16(pv);
        Ph[row * NN + tid + i * 256] = h;
        Pl[row * NN + tid + i * 256] = __float2bfloat16(pv - __bfloat162float(h));
    }
}

// ---------------------------------------------------------------------------
// Launch
// ---------------------------------------------------------------------------
extern "C" void kernel_launch(void* const* d_in, const int* in_sizes, int n_in,
                              void* d_out, int out_size) {
    const float* x  = (const float*)d_in[0];
    const float* Wq = (const float*)d_in[1];
    const float* bq = (const float*)d_in[2];
    const float* Wk = (const float*)d_in[3];
    const float* bk = (const float*)d_in[4];
    const float* Wv = (const float*)d_in[5];
    const float* bv = (const float*)d_in[6];
    float* out = (float*)d_out;

    __nv_bfloat16 *xh, *xl, *Wqh, *Wql, *Wkh, *Wkl, *Wvh, *Wvl;
    __nv_bfloat16 *Qh, *Ql, *Kh, *Kl, *Vh, *Vl, *Ph, *Pl;
    float* S;
    cudaGetSymbolAddress((void**)&xh, g_xh);
    cudaGetSymbolAddress((void**)&xl, g_xl);
    cudaGetSymbolAddress((void**)&Wqh, g_Wqh);
    cudaGetSymbolAddress((void**)&Wql, g_Wql);
    cudaGetSymbolAddress((void**)&Wkh, g_Wkh);
    cudaGetSymbolAddress((void**)&Wkl, g_Wkl);
    cudaGetSymbolAddress((void**)&Wvh, g_Wvh);
    cudaGetSymbolAddress((void**)&Wvl, g_Wvl);
    cudaGetSymbolAddress((void**)&Qh, g_Qh);
    cudaGetSymbolAddress((void**)&Ql, g_Ql);
    cudaGetSymbolAddress((void**)&Kh, g_Kh);
    cudaGetSymbolAddress((void**)&Kl, g_Kl);
    cudaGetSymbolAddress((void**)&Vh, g_Vh);
    cudaGetSymbolAddress((void**)&Vl, g_Vl);
    cudaGetSymbolAddress((void**)&Ph, g_Ph);
    cudaGetSymbolAddress((void**)&Pl, g_Pl);
    cudaGetSymbolAddress((void**)&S, g_S);

    const int SMEM = 3 * 32768;
    cudaFuncSetAttribute(tc_gemm<true, true, true>,
                         cudaFuncAttributeMaxDynamicSharedMemorySize, SMEM);
    cudaFuncSetAttribute(tc_gemm<true, false, false>,
                         cudaFuncAttributeMaxDynamicSharedMemorySize, SMEM);
    cudaFuncSetAttribute(tc_gemm<false, false, false>,
                         cudaFuncAttributeMaxDynamicSharedMemorySize, SMEM);

    // prep: split x and weights
    int n4x = BB * NN * CC / 4;
    split_planes<<<n4x / 256, 256>>>(x, xh, xl, n4x);
    int n4w = CC * CC / 4;
    split_planes<<<n4w / 256, 256>>>(Wq, Wqh, Wql, n4w);
    split_planes<<<n4w / 256, 256>>>(Wk, Wkh, Wkl, n4w);
    split_planes<<<n4w / 256, 256>>>(Wv, Wvh, Wvl, n4w);

    dim3 thr(256);

    // QKV projections -> split planes directly (no fp32 intermediates)
    dim3 gqkv(CC / 128, (BB * NN) / 128, 1);
    tc_gemm<true, true, true><<<gqkv, thr, SMEM>>>(
        xh, xl, Wqh, Wql, nullptr, Qh, Ql, bq, CC, CC, CC, CC, 0, 0, 0, 1.0f);
    tc_gemm<true, true, true><<<gqkv, thr, SMEM>>>(
        xh, xl, Wkh, Wkl, nullptr, Kh, Kl, bk, CC, CC, CC, CC, 0, 0, 0, 1.0f);
    tc_gemm<true, true, true><<<gqkv, thr, SMEM>>>(
        xh, xl, Wvh, Wvl, nullptr, Vh, Vl, bv, CC, CC, CC, CC, 0, 0, 0, 1.0f);

    // S = Q K^T / sqrt(C)  (fp32 out for exact top-k)
    dim3 gs(NN / 128, NN / 128, BB);
    tc_gemm<true, false, false><<<gs, thr, SMEM>>>(
        Qh, Ql, Kh, Kl, S, nullptr, nullptr, nullptr, NN, CC, CC, CC,
        (long long)NN * CC, (long long)NN * CC, (long long)NN * NN, 0.03125f);

    // exact top-k + softmax -> P split planes
    topk_softmax<<<BB * NN, 256>>>(S, Ph, Pl);

    // O = P V  (NN path: B = V [seq][dim])
    dim3 go(CC / 128, NN / 128, BB);
    tc_gemm<false, false, false><<<go, thr, SMEM>>>(
        Ph, Pl, Vh, Vl, out, nullptr, nullptr, nullptr, CC, NN, CC, NN,
        (long long)NN * NN, (long long)NN * CC, (long long)NN * CC, 1.0f);
}

// round 12
// speedup vs baseline: 1.4588x; 1.1583x over previous
#include <cuda_runtime.h>
#include <cuda_bf16.h>
#include <cstdint>

// Problem constants
#define BB 8
#define NN 2048
#define CC 1024
#define KKEEP 1638

// Scratch (allocation-free rule: __device__ globals) — all operands pre-split bf16
__device__ __nv_bfloat16 g_xh[BB * NN * CC], g_xl[BB * NN * CC];
__device__ __nv_bfloat16 g_Wqh[CC * CC], g_Wql[CC * CC];
__device__ __nv_bfloat16 g_Wkh[CC * CC], g_Wkl[CC * CC];
__device__ __nv_bfloat16 g_Wvh[CC * CC], g_Wvl[CC * CC];
__device__ __nv_bfloat16 g_Qh[BB * NN * CC], g_Ql[BB * NN * CC];
__device__ __nv_bfloat16 g_Kh[BB * NN * CC], g_Kl[BB * NN * CC];
__device__ __nv_bfloat16 g_Vh[BB * NN * CC], g_Vl[BB * NN * CC];
__device__ float g_S[(size_t)BB * NN * NN];
__device__ __nv_bfloat16 g_Ph[(size_t)BB * NN * NN], g_Pl[(size_t)BB * NN * NN];

// ---------------------------------------------------------------------------
// helpers
// ---------------------------------------------------------------------------
__device__ __forceinline__ void split2(float v0, float v1, unsigned& hi, unsigned& lo) {
    __nv_bfloat162 h = __floats2bfloat162_rn(v0, v1);
    float2 hf = __bfloat1622float2(h);
    __nv_bfloat162 l = __floats2bfloat162_rn(v0 - hf.x, v1 - hf.y);
    hi = *reinterpret_cast<unsigned*>(&h);
    lo = *reinterpret_cast<unsigned*>(&l);
}

__device__ __forceinline__ void mma16(float* c, const unsigned* a, const unsigned* b) {
    asm volatile(
        "mma.sync.aligned.m16n8k16.row.col.f32.bf16.bf16.f32 "
        "{%0,%1,%2,%3}, {%4,%5,%6,%7}, {%8,%9}, {%0,%1,%2,%3};"
        : "+f"(c[0]), "+f"(c[1]), "+f"(c[2]), "+f"(c[3])
        : "r"(a[0]), "r"(a[1]), "r"(a[2]), "r"(a[3]), "r"(b[0]), "r"(b[1]));
}
__device__ __forceinline__ void ldm4(unsigned* r, unsigned addr) {
    asm volatile("ldmatrix.sync.aligned.m8n8.x4.shared.b16 {%0,%1,%2,%3}, [%4];"
                 : "=r"(r[0]), "=r"(r[1]), "=r"(r[2]), "=r"(r[3]) : "r"(addr));
}
__device__ __forceinline__ void ldm4t(unsigned* r, unsigned addr) {
    asm volatile("ldmatrix.sync.aligned.m8n8.x4.trans.shared.b16 {%0,%1,%2,%3}, [%4];"
                 : "=r"(r[0]), "=r"(r[1]), "=r"(r[2]), "=r"(r[3]) : "r"(addr));
}
__device__ __forceinline__ void cpa(unsigned s, const void* g) {
    asm volatile("cp.async.cg.shared.global [%0], [%1], 16;" :: "r"(s), "l"(g));
}

// ---------------------------------------------------------------------------
// prep: split fp32 array into bf16 hi/lo planes
// ---------------------------------------------------------------------------
__global__ void split_planes(const float* __restrict__ src,
                             __nv_bfloat16* __restrict__ h,
                             __nv_bfloat16* __restrict__ l, int n4) {
    int i = blockIdx.x * blockDim.x + threadIdx.x;
    if (i < n4) {
        float4 v = ((const float4*)src)[i];
        unsigned h0, l0, h1, l1;
        split2(v.x, v.y, h0, l0);
        split2(v.z, v.w, h1, l1);
        ((uint2*)h)[i] = make_uint2(h0, h1);
        ((uint2*)l)[i] = make_uint2(l0, l1);
    }
}

// ---------------------------------------------------------------------------
// GEMM: pre-split bf16 planes; cp.async 3-stage; ldmatrix + mma.
// CTA tile 128x128, K_tile=32, 256 threads, 8 warps (2x4) each 64x32.
// 3-term split: ah*bh + ah*bl + al*bh (fp32 accum).
//   TRANSB: true -> B planes are [N][K] (NT); false -> [K][N] (NN, ldmatrix.trans)
// smem stage (32KB): AH(8K) AL(8K) BH(8K) BL(8K)
//   A/NT-B rows: 64B, chunk swizzle c ^ ((r>>1)&3)
//   NN-B rows: 256B, chunk swizzle c ^ (r&7)
// cp.async for stage kt+2 is interleaved into the MMA phases of stage kt.
// ---------------------------------------------------------------------------
template <bool TRANSB, bool BIAS, bool SPLITOUT>
__global__ void __launch_bounds__(256, 2)
tc_gemm(const __nv_bfloat16* __restrict__ Ah, const __nv_bfloat16* __restrict__ Al,
        const __nv_bfloat16* __restrict__ Bh, const __nv_bfloat16* __restrict__ Bl,
        float* __restrict__ C, __nv_bfloat16* __restrict__ Ch,
        __nv_bfloat16* __restrict__ Cl, const float* __restrict__ bias,
        int Nld, int lda, int ldb, int K,
        long long sA, long long sB, long long sC, float scale) {
    extern __shared__ __align__(16) unsigned char dsm[];
    const unsigned stiles = (unsigned)__cvta_generic_to_shared(dsm);

    Ah += (size_t)blockIdx.z * sA;
    Al += (size_t)blockIdx.z * sA;
    Bh += (size_t)blockIdx.z * sB;
    Bl += (size_t)blockIdx.z * sB;
    if (SPLITOUT) { Ch += (size_t)blockIdx.z * sC; Cl += (size_t)blockIdx.z * sC; }
    else          { C  += (size_t)blockIdx.z * sC; }

    const int t = threadIdx.x;
    const int lane = t & 31;
    const int warp = t >> 5;
    const int wm = warp & 1;
    const int wn = warp >> 1;
    const int g = lane >> 2;
    const int tg = lane & 3;

    const int m0 = blockIdx.y * 128;
    const int n0 = blockIdx.x * 128;
    const int aBase = wm * 64;
    const int bBase = wn * 32;

    float acc[4][4][4];
#pragma unroll
    for (int i = 0; i < 4; i++)
#pragma unroll
        for (int j = 0; j < 4; j++)
#pragma unroll
            for (int r = 0; r < 4; r++) acc[i][j][r] = 0.f;

    const int NK = K / 32;

    // ---- per-thread cp.async src/dst, computed once ----
    unsigned soA[2], soB[2];
    size_t goA[2], goB[2];
#pragma unroll
    for (int p = 0; p < 2; p++) {
        int idx = t + p * 256;
        {
            int r = idx >> 2, c = idx & 3;
            soA[p] = (unsigned)(r * 64 + ((c ^ ((r >> 1) & 3)) << 4));
            goA[p] = (size_t)(m0 + r) * lda + c * 8;
        }
        if (TRANSB) {
            int r = idx >> 2, c = idx & 3;
            soB[p] = 16384u + (unsigned)(r * 64 + ((c ^ ((r >> 1) & 3)) << 4));
            goB[p] = (size_t)(n0 + r) * ldb + c * 8;
        } else {
            int r = idx >> 4, c = idx & 15;
            soB[p] = 16384u + (unsigned)(r * 256 + ((c ^ (r & 7)) << 4));
            goB[p] = (size_t)r * ldb + n0 + c * 8;
        }
    }

    auto cpa_A = [&](int kt, unsigned off) {
        const size_t kadd = (size_t)kt * 32;
#pragma unroll
        for (int p = 0; p < 2; p++) {
            cpa(off + soA[p], Ah + goA[p] + kadd);
            cpa(off + soA[p] + 8192u, Al + goA[p] + kadd);
        }
    };
    auto cpa_B = [&](int kt, unsigned off) {
        const size_t kadd = TRANSB ? (size_t)kt * 32 : (size_t)kt * 32 * ldb;
#pragma unroll
        for (int p = 0; p < 2; p++) {
            cpa(off + soB[p], Bh + goB[p] + kadd);
            cpa(off + soB[p] + 8192u, Bl + goB[p] + kadd);
        }
    };

    // ---- per-thread ldmatrix offsets (relative to stage base) ----
    unsigned axk[4][2];
#pragma unroll
    for (int mt = 0; mt < 4; mt++) {
        int ar = aBase + mt * 16 + (lane & 15);
        int rsw = (ar >> 1) & 3;
        int c0 = lane >> 4;
        axk[mt][0] = (unsigned)(ar * 64 + ((c0 ^ rsw) << 4));
        axk[mt][1] = (unsigned)(ar * 64 + (((c0 + 2) ^ rsw) << 4));
    }
    unsigned bxk[2][2];
    if (TRANSB) {
#pragma unroll
        for (int p = 0; p < 2; p++) {
            int br = bBase + p * 16 + (lane & 7) + (lane >> 4) * 8;
            int rsw = (br >> 1) & 3;
            int c0 = (lane >> 3) & 1;
            bxk[p][0] = 16384u + (unsigned)(br * 64 + ((c0 ^ rsw) << 4));
            bxk[p][1] = 16384u + (unsigned)(br * 64 + (((c0 + 2) ^ rsw) << 4));
        }
    } else {
        int kr = (lane & 7) + ((lane >> 3) & 1) * 8;
#pragma unroll
        for (int p = 0; p < 2; p++) {
            int c = bBase / 8 + (lane >> 4) + 2 * p;
            unsigned b0 = 16384u + (unsigned)(kr * 256 + ((c ^ (kr & 7)) << 4));
            bxk[p][0] = b0;
            bxk[p][1] = b0 + 4096u;   // +16 k-rows
        }
    }

    // ---- prologue: stages 0 and 1 ----
    cpa_A(0, stiles);
    cpa_B(0, stiles);
    asm volatile("cp.async.commit_group;" ::: "memory");
    cpa_A(1, stiles + 32768u);
    cpa_B(1, stiles + 32768u);
    asm volatile("cp.async.commit_group;" ::: "memory");

    unsigned coff = stiles;                 // compute stage base
    unsigned loff = stiles + 65536u;        // load stage base (kt+2)
    const unsigned topoff = stiles + 65536u;

    for (int kt = 0; kt < NK; kt++) {
        asm volatile("cp.async.wait_group 1;" ::: "memory");
        __syncthreads();
        const bool more = (kt + 2) < NK;

#pragma unroll
        for (int ks = 0; ks < 2; ks++) {
            unsigned ah[4][4], bh[2][4], bl[2][4];
#pragma unroll
            for (int mt = 0; mt < 4; mt++) ldm4(ah[mt], coff + axk[mt][ks]);
#pragma unroll
            for (int p = 0; p < 2; p++) {
                if (TRANSB) ldm4(bh[p], coff + bxk[p][ks]);
                else        ldm4t(bh[p], coff + bxk[p][ks]);
            }
#pragma unroll
            for (int p = 0; p < 2; p++) {
                if (TRANSB) ldm4(bl[p], coff + bxk[p][ks] + 8192u);
                else        ldm4t(bl[p], coff + bxk[p][ks] + 8192u);
            }
            // interleave next-stage loads between fragment loads and MMAs
            if (more) { if (ks == 0) cpa_A(kt + 2, loff); else cpa_B(kt + 2, loff); }

#pragma unroll
            for (int mt = 0; mt < 4; mt++)
#pragma unroll
                for (int nt = 0; nt < 4; nt++)
                    mma16(acc[mt][nt], ah[mt], &bh[nt >> 1][(nt & 1) * 2]);
#pragma unroll
            for (int mt = 0; mt < 4; mt++)
#pragma unroll
                for (int nt = 0; nt < 4; nt++)
                    mma16(acc[mt][nt], ah[mt], &bl[nt >> 1][(nt & 1) * 2]);

            unsigned al[4][4];
#pragma unroll
            for (int mt = 0; mt < 4; mt++) ldm4(al[mt], coff + axk[mt][ks] + 8192u);
#pragma unroll
            for (int mt = 0; mt < 4; mt++)
#pragma unroll
                for (int nt = 0; nt < 4; nt++)
                    mma16(acc[mt][nt], al[mt], &bh[nt >> 1][(nt & 1) * 2]);
        }

        asm volatile("cp.async.commit_group;" ::: "memory");
        coff = (coff == topoff) ? stiles : coff + 32768u;
        loff = (loff == topoff) ? stiles : loff + 32768u;
    }

    // ---- epilogue ----
#pragma unroll
    for (int mt = 0; mt < 4; mt++) {
        int m = m0 + aBase + mt * 16 + g;
#pragma unroll
        for (int nt = 0; nt < 4; nt++) {
            int n = n0 + bBase + nt * 8 + tg * 2;
            float b0 = 0.f, b1 = 0.f;
            if (BIAS) { b0 = bias[n]; b1 = bias[n + 1]; }
            float v00 = acc[mt][nt][0] * scale + b0;
            float v01 = acc[mt][nt][1] * scale + b1;
            float v10 = acc[mt][nt][2] * scale + b0;
            float v11 = acc[mt][nt][3] * scale + b1;
            if (SPLITOUT) {
                unsigned h, l;
                split2(v00, v01, h, l);
                *(unsigned*)&Ch[(size_t)m * Nld + n] = h;
                *(unsigned*)&Cl[(size_t)m * Nld + n] = l;
                split2(v10, v11, h, l);
                *(unsigned*)&Ch[(size_t)(m + 8) * Nld + n] = h;
                *(unsigned*)&Cl[(size_t)(m + 8) * Nld + n] = l;
            } else {
                *(float2*)&C[(size_t)m * Nld + n] = make_float2(v00, v01);
                *(float2*)&C[(size_t)(m + 8) * Nld + n] = make_float2(v10, v11);
            }
        }
    }
}

// ---------------------------------------------------------------------------
// Per-row exact top-k threshold (4-pass MSB radix select, warp-parallel scan)
// + masked softmax. One block (256 threads) per row. Masked entries -> 0.
// ---------------------------------------------------------------------------
__device__ __forceinline__ unsigned f2u(float f) {
    unsigned b = __float_as_uint(f);
    return (b & 0x80000000u) ? ~b : (b | 0x80000000u);
}
__device__ __forceinline__ float u2f(unsigned u) {
    unsigned b = (u & 0x80000000u) ? (u & 0x7fffffffu) : ~u;
    return __uint_as_float(b);
}

__global__ void __launch_bounds__(256) topk_softmax(const float* __restrict__ S,
                                                    __nv_bfloat16* __restrict__ Ph,
                                                    __nv_bfloat16* __restrict__ Pl) {
    const size_t row = blockIdx.x;
    const float* p = S + row * NN;
    const int tid = threadIdx.x;

    __shared__ int hist[256];
    __shared__ int s_digit, s_rem;
    __shared__ unsigned s_warpk[8];
    __shared__ float s_warpf[8];
    __shared__ float s_sum;

    // vectorized load: thread owns elements tid*4..+3 and 1024+tid*4..+3
    float val[8];
    unsigned key[8];
    {
        float4 v0 = *(const float4*)&p[tid * 4];
        float4 v1 = *(const float4*)&p[1024 + tid * 4];
        val[0] = v0.x; val[1] = v0.y; val[2] = v0.z; val[3] = v0.w;
        val[4] = v1.x; val[5] = v1.y; val[6] = v1.z; val[7] = v1.w;
    }
    unsigned lmax = 0;
#pragma unroll
    for (int i = 0; i < 8; i++) {
        key[i] = f2u(val[i]);
        lmax = max(lmax, key[i]);
    }

    lmax = __reduce_max_sync(0xffffffffu, lmax);
    if ((tid & 31) == 0) s_warpk[tid >> 5] = lmax;
    __syncthreads();
    if (tid == 0) {
        unsigned m = s_warpk[0];
#pragma unroll
        for (int w = 1; w < 8; w++) m = max(m, s_warpk[w]);
        s_warpk[0] = m;
        s_rem = KKEEP;
    }

    unsigned prefix = 0, pmask = 0;
    for (int shift = 24; shift >= 0; shift -= 8) {
        hist[tid] = 0;
        __syncthreads();
#pragma unroll
        for (int i = 0; i < 8; i++)
            if ((key[i] & pmask) == prefix)
                atomicAdd(&hist[(key[i] >> shift) & 255], 1);
        __syncthreads();
        if (tid < 32) {
            const int base = tid * 8;
            int c[8], tot = 0;
#pragma unroll
            for (int j = 0; j < 8; j++) { c[j] = hist[base + j]; tot += c[j]; }
            // inclusive suffix-sum across lanes (lane covers digits base..base+7)
            int incl = tot;
#pragma unroll
            for (int o = 1; o < 32; o <<= 1) {
                int u = __shfl_down_sync(0xffffffffu, incl, o);
                if (tid + o < 32) incl += u;
            }
            const int excl = incl - tot;       // sum over digits > base+7
            const int remk = s_rem;
            if (excl < remk && excl + tot >= remk) {
                int cum = excl, j = 7;
#pragma unroll
                for (; j > 0; j--) {
                    cum += c[j];
                    if (cum >= remk) break;
                }
                if (cum < remk) cum += c[0];   // j==0 fallthrough
                s_digit = base + j;
                s_rem = remk - (cum - c[j]);
            }
        }
        __syncthreads();
        prefix |= ((unsigned)s_digit) << shift;
        pmask |= 0xFFu << shift;
    }
    const unsigned thr = prefix;
    const float mval = u2f(s_warpk[0]);

    float e[8];
    float lsum = 0.f;
#pragma unroll
    for (int i = 0; i < 8; i++) {
        if (key[i] >= thr) {
            e[i] = __expf(val[i] - mval);
            lsum += e[i];
        } else {
            e[i] = 0.f;
        }
    }
#pragma unroll
    for (int o = 16; o > 0; o >>= 1) lsum += __shfl_down_sync(0xffffffffu, lsum, o);
    if ((tid & 31) == 0) s_warpf[tid >> 5] = lsum;
    __syncthreads();
    if (tid == 0) {
        float s = 0.f;
#pragma unroll
        for (int w = 0; w < 8; w++) s += s_warpf[w];
        s_sum = s;
    }
    __syncthreads();
    const float inv = 1.0f / s_sum;

    const size_t ob = row * NN + tid * 4;
    {
        unsigned h0, l0, h1, l1;
        split2(e[0] * inv, e[1] * inv, h0, l0);
        split2(e[2] * inv, e[3] * inv, h1, l1);
        *(uint2*)&Ph[ob] = make_uint2(h0, h1);
        *(uint2*)&Pl[ob] = make_uint2(l0, l1);
        split2(e[4] * inv, e[5] * inv, h0, l0);
        split2(e[6] * inv, e[7] * inv, h1, l1);
        *(uint2*)&Ph[ob + 1024] = make_uint2(h0, h1);
        *(uint2*)&Pl[ob + 1024] = make_uint2(l0, l1);
    }
}

// ---------------------------------------------------------------------------
// Launch
// ---------------------------------------------------------------------------
extern "C" void kernel_launch(void* const* d_in, const int* in_sizes, int n_in,
                              void* d_out, int out_size) {
    const float* x  = (const float*)d_in[0];
    const float* Wq = (const float*)d_in[1];
    const float* bq = (const float*)d_in[2];
    const float* Wk = (const float*)d_in[3];
    const float* bk = (const float*)d_in[4];
    const float* Wv = (const float*)d_in[5];
    const float* bv = (const float*)d_in[6];
    float* out = (float*)d_out;

    __nv_bfloat16 *xh, *xl, *Wqh, *Wql, *Wkh, *Wkl, *Wvh, *Wvl;
    __nv_bfloat16 *Qh, *Ql, *Kh, *Kl, *Vh, *Vl, *Ph, *Pl;
    float* S;
    cudaGetSymbolAddress((void**)&xh, g_xh);
    cudaGetSymbolAddress((void**)&xl, g_xl);
    cudaGetSymbolAddress((void**)&Wqh, g_Wqh);
    cudaGetSymbolAddress((void**)&Wql, g_Wql);
    cudaGetSymbolAddress((void**)&Wkh, g_Wkh);
    cudaGetSymbolAddress((void**)&Wkl, g_Wkl);
    cudaGetSymbolAddress((void**)&Wvh, g_Wvh);
    cudaGetSymbolAddress((void**)&Wvl, g_Wvl);
    cudaGetSymbolAddress((void**)&Qh, g_Qh);
    cudaGetSymbolAddress((void**)&Ql, g_Ql);
    cudaGetSymbolAddress((void**)&Kh, g_Kh);
    cudaGetSymbolAddress((void**)&Kl, g_Kl);
    cudaGetSymbolAddress((void**)&Vh, g_Vh);
    cudaGetSymbolAddress((void**)&Vl, g_Vl);
    cudaGetSymbolAddress((void**)&Ph, g_Ph);
    cudaGetSymbolAddress((void**)&Pl, g_Pl);
    cudaGetSymbolAddress((void**)&S, g_S);

    const int SMEM = 3 * 32768;
    cudaFuncSetAttribute(tc_gemm<true, true, true>,
                         cudaFuncAttributeMaxDynamicSharedMemorySize, SMEM);
    cudaFuncSetAttribute(tc_gemm<true, false, false>,
                         cudaFuncAttributeMaxDynamicSharedMemorySize, SMEM);
    cudaFuncSetAttribute(tc_gemm<false, false, false>,
                         cudaFuncAttributeMaxDynamicSharedMemorySize, SMEM);

    // prep: split x and weights
    int n4x = BB * NN * CC / 4;
    split_planes<<<n4x / 256, 256>>>(x, xh, xl, n4x);
    int n4w = CC * CC / 4;
    split_planes<<<n4w / 256, 256>>>(Wq, Wqh, Wql, n4w);
    split_planes<<<n4w / 256, 256>>>(Wk, Wkh, Wkl, n4w);
    split_planes<<<n4w / 256, 256>>>(Wv, Wvh, Wvl, n4w);

    dim3 thr(256);

    // QKV projections -> split planes directly
    dim3 gqkv(CC / 128, (BB * NN) / 128, 1);
    tc_gemm<true, true, true><<<gqkv, thr, SMEM>>>(
        xh, xl, Wqh, Wql, nullptr, Qh, Ql, bq, CC, CC, CC, CC, 0, 0, 0, 1.0f);
    tc_gemm<true, true, true><<<gqkv, thr, SMEM>>>(
        xh, xl, Wkh, Wkl, nullptr, Kh, Kl, bk, CC, CC, CC, CC, 0, 0, 0, 1.0f);
    tc_gemm<true, true, true><<<gqkv, thr, SMEM>>>(
        xh, xl, Wvh, Wvl, nullptr, Vh, Vl, bv, CC, CC, CC, CC, 0, 0, 0, 1.0f);

    // S = Q K^T / sqrt(C)  (fp32 out for exact top-k)
    dim3 gs(NN / 128, NN / 128, BB);
    tc_gemm<true, false, false><<<gs, thr, SMEM>>>(
        Qh, Ql, Kh, Kl, S, nullptr, nullptr, nullptr, NN, CC, CC, CC,
        (long long)NN * CC, (long long)NN * CC, (long long)NN * NN, 0.03125f);

    // exact top-k + softmax -> P split planes
    topk_softmax<<<BB * NN, 256>>>(S, Ph, Pl);

    // O = P V  (NN path)
    dim3 go(CC / 128, NN / 128, BB);
    tc_gemm<false, false, false><<<go, thr, SMEM>>>(
        Ph, Pl, Vh, Vl, out, nullptr, nullptr, nullptr, CC, NN, CC, NN,
        (long long)NN * NN, (long long)NN * CC, (long long)NN * CC, 1.0f);
}

// round 13
// speedup vs baseline: 1.6518x; 1.1323x over previous
#include <cuda_runtime.h>
#include <cuda_fp16.h>
#include <cstdint>

// Problem constants
#define BB 8
#define NN 2048
#define CC 1024
#define KKEEP 1638

// Scratch (allocation-free rule: __device__ globals) — all operands pre-split fp16
__device__ __half g_xh[BB * NN * CC], g_xl[BB * NN * CC];
__device__ __half g_Wqh[CC * CC], g_Wql[CC * CC];
__device__ __half g_Wkh[CC * CC], g_Wkl[CC * CC];
__device__ __half g_Wvh[CC * CC], g_Wvl[CC * CC];
__device__ __half g_Qh[BB * NN * CC], g_Ql[BB * NN * CC];
__device__ __half g_Kh[BB * NN * CC], g_Kl[BB * NN * CC];
__device__ __half g_Vh[BB * NN * CC], g_Vl[BB * NN * CC];
__device__ float g_S[(size_t)BB * NN * NN];
__device__ __half g_Ph[(size_t)BB * NN * NN], g_Pl[(size_t)BB * NN * NN];

// ---------------------------------------------------------------------------
// helpers
// ---------------------------------------------------------------------------
__device__ __forceinline__ void split2(float v0, float v1, unsigned& hi, unsigned& lo) {
    __half2 h = __floats2half2_rn(v0, v1);
    float2 hf = __half22float2(h);
    __half2 l = __floats2half2_rn(v0 - hf.x, v1 - hf.y);
    hi = *reinterpret_cast<unsigned*>(&h);
    lo = *reinterpret_cast<unsigned*>(&l);
}

__device__ __forceinline__ void mma16(float* c, const unsigned* a, const unsigned* b) {
    asm volatile(
        "mma.sync.aligned.m16n8k16.row.col.f32.f16.f16.f32 "
        "{%0,%1,%2,%3}, {%4,%5,%6,%7}, {%8,%9}, {%0,%1,%2,%3};"
        : "+f"(c[0]), "+f"(c[1]), "+f"(c[2]), "+f"(c[3])
        : "r"(a[0]), "r"(a[1]), "r"(a[2]), "r"(a[3]), "r"(b[0]), "r"(b[1]));
}
__device__ __forceinline__ void ldm4(unsigned* r, unsigned addr) {
    asm volatile("ldmatrix.sync.aligned.m8n8.x4.shared.b16 {%0,%1,%2,%3}, [%4];"
                 : "=r"(r[0]), "=r"(r[1]), "=r"(r[2]), "=r"(r[3]) : "r"(addr));
}
__device__ __forceinline__ void ldm4t(unsigned* r, unsigned addr) {
    asm volatile("ldmatrix.sync.aligned.m8n8.x4.trans.shared.b16 {%0,%1,%2,%3}, [%4];"
                 : "=r"(r[0]), "=r"(r[1]), "=r"(r[2]), "=r"(r[3]) : "r"(addr));
}
__device__ __forceinline__ void cpa(unsigned s, const void* g) {
    asm volatile("cp.async.cg.shared.global [%0], [%1], 16;" :: "r"(s), "l"(g));
}

// ---------------------------------------------------------------------------
// prep: split fp32 array into fp16 hi/lo planes
// ---------------------------------------------------------------------------
__global__ void split_planes(const float* __restrict__ src,
                             __half* __restrict__ h,
                             __half* __restrict__ l, int n4) {
    int i = blockIdx.x * blockDim.x + threadIdx.x;
    if (i < n4) {
        float4 v = ((const float4*)src)[i];
        unsigned h0, l0, h1, l1;
        split2(v.x, v.y, h0, l0);
        split2(v.z, v.w, h1, l1);
        ((uint2*)h)[i] = make_uint2(h0, h1);
        ((uint2*)l)[i] = make_uint2(l0, l1);
    }
}

// ---------------------------------------------------------------------------
// GEMM: pre-split fp16 planes; cp.async 3-stage; ldmatrix + mma.
// CTA tile 128x128, K_tile=32, 256 threads, 8 warps (2x4) each 64x32.
//   TERMS==3: ah*bh + ah*bl + al*bh (fp32-grade, residual ~2^-22)
//   TERMS==2: ah*bh + al*bh (A fully represented, B hi-only; err ~2^-12 |b|)
//   TRANSB: true -> B planes are [N][K] (NT); false -> [K][N] (NN, ldmatrix.trans)
// smem stage: AH(8K) AL(8K) BH(8K) [BL(8K) if TERMS==3]
//   A/NT-B rows: 64B, chunk swizzle c ^ ((r>>1)&3)
//   NN-B rows: 256B, chunk swizzle c ^ (r&7)
// cp.async for stage kt+2 interleaved into MMA phases of stage kt.
// ---------------------------------------------------------------------------
template <bool TRANSB, bool BIAS, bool SPLITOUT, int TERMS>
__global__ void __launch_bounds__(256, 2)
tc_gemm(const __half* __restrict__ Ah, const __half* __restrict__ Al,
        const __half* __restrict__ Bh, const __half* __restrict__ Bl,
        float* __restrict__ C, __half* __restrict__ Ch,
        __half* __restrict__ Cl, const float* __restrict__ bias,
        int Nld, int lda, int ldb, int K,
        long long sA, long long sB, long long sC, float scale) {
    constexpr unsigned STG = (TERMS == 3) ? 32768u : 24576u;
    extern __shared__ __align__(16) unsigned char dsm[];
    const unsigned stiles = (unsigned)__cvta_generic_to_shared(dsm);

    Ah += (size_t)blockIdx.z * sA;
    Al += (size_t)blockIdx.z * sA;
    Bh += (size_t)blockIdx.z * sB;
    if (TERMS == 3) Bl += (size_t)blockIdx.z * sB;
    if (SPLITOUT) { Ch += (size_t)blockIdx.z * sC; Cl += (size_t)blockIdx.z * sC; }
    else          { C  += (size_t)blockIdx.z * sC; }

    const int t = threadIdx.x;
    const int lane = t & 31;
    const int warp = t >> 5;
    const int wm = warp & 1;
    const int wn = warp >> 1;
    const int g = lane >> 2;
    const int tg = lane & 3;

    const int m0 = blockIdx.y * 128;
    const int n0 = blockIdx.x * 128;
    const int aBase = wm * 64;
    const int bBase = wn * 32;

    float acc[4][4][4];
#pragma unroll
    for (int i = 0; i < 4; i++)
#pragma unroll
        for (int j = 0; j < 4; j++)
#pragma unroll
            for (int r = 0; r < 4; r++) acc[i][j][r] = 0.f;

    const int NK = K / 32;

    // ---- per-thread cp.async src/dst, computed once ----
    unsigned soA[2], soB[2];
    size_t goA[2], goB[2];
#pragma unroll
    for (int p = 0; p < 2; p++) {
        int idx = t + p * 256;
        {
            int r = idx >> 2, c = idx & 3;
            soA[p] = (unsigned)(r * 64 + ((c ^ ((r >> 1) & 3)) << 4));
            goA[p] = (size_t)(m0 + r) * lda + c * 8;
        }
        if (TRANSB) {
            int r = idx >> 2, c = idx & 3;
            soB[p] = 16384u + (unsigned)(r * 64 + ((c ^ ((r >> 1) & 3)) << 4));
            goB[p] = (size_t)(n0 + r) * ldb + c * 8;
        } else {
            int r = idx >> 4, c = idx & 15;
            soB[p] = 16384u + (unsigned)(r * 256 + ((c ^ (r & 7)) << 4));
            goB[p] = (size_t)r * ldb + n0 + c * 8;
        }
    }

    auto cpa_A = [&](int kt, unsigned off) {
        const size_t kadd = (size_t)kt * 32;
#pragma unroll
        for (int p = 0; p < 2; p++) {
            cpa(off + soA[p], Ah + goA[p] + kadd);
            cpa(off + soA[p] + 8192u, Al + goA[p] + kadd);
        }
    };
    auto cpa_B = [&](int kt, unsigned off) {
        const size_t kadd = TRANSB ? (size_t)kt * 32 : (size_t)kt * 32 * ldb;
#pragma unroll
        for (int p = 0; p < 2; p++) {
            cpa(off + soB[p], Bh + goB[p] + kadd);
            if (TERMS == 3) cpa(off + soB[p] + 8192u, Bl + goB[p] + kadd);
        }
    };

    // ---- per-thread ldmatrix offsets (relative to stage base) ----
    unsigned axk[4][2];
#pragma unroll
    for (int mt = 0; mt < 4; mt++) {
        int ar = aBase + mt * 16 + (lane & 15);
        int rsw = (ar >> 1) & 3;
        int c0 = lane >> 4;
        axk[mt][0] = (unsigned)(ar * 64 + ((c0 ^ rsw) << 4));
        axk[mt][1] = (unsigned)(ar * 64 + (((c0 + 2) ^ rsw) << 4));
    }
    unsigned bxk[2][2];
    if (TRANSB) {
#pragma unroll
        for (int p = 0; p < 2; p++) {
            int br = bBase + p * 16 + (lane & 7) + (lane >> 4) * 8;
            int rsw = (br >> 1) & 3;
            int c0 = (lane >> 3) & 1;
            bxk[p][0] = 16384u + (unsigned)(br * 64 + ((c0 ^ rsw) << 4));
            bxk[p][1] = 16384u + (unsigned)(br * 64 + (((c0 + 2) ^ rsw) << 4));
        }
    } else {
        int kr = (lane & 7) + ((lane >> 3) & 1) * 8;
#pragma unroll
        for (int p = 0; p < 2; p++) {
            int c = bBase / 8 + (lane >> 4) + 2 * p;
            unsigned b0 = 16384u + (unsigned)(kr * 256 + ((c ^ (kr & 7)) << 4));
            bxk[p][0] = b0;
            bxk[p][1] = b0 + 4096u;   // +16 k-rows
        }
    }

    // ---- prologue: stages 0 and 1 ----
    cpa_A(0, stiles);
    cpa_B(0, stiles);
    asm volatile("cp.async.commit_group;" ::: "memory");
    cpa_A(1, stiles + STG);
    cpa_B(1, stiles + STG);
    asm volatile("cp.async.commit_group;" ::: "memory");

    unsigned coff = stiles;                 // compute stage base
    unsigned loff = stiles + 2 * STG;       // load stage base (kt+2)
    const unsigned topoff = stiles + 2 * STG;

    for (int kt = 0; kt < NK; kt++) {
        asm volatile("cp.async.wait_group 1;" ::: "memory");
        __syncthreads();
        const bool more = (kt + 2) < NK;

#pragma unroll
        for (int ks = 0; ks < 2; ks++) {
            unsigned ah[4][4], bh[2][4], bl[2][4];
#pragma unroll
            for (int mt = 0; mt < 4; mt++) ldm4(ah[mt], coff + axk[mt][ks]);
#pragma unroll
            for (int p = 0; p < 2; p++) {
                if (TRANSB) ldm4(bh[p], coff + bxk[p][ks]);
                else        ldm4t(bh[p], coff + bxk[p][ks]);
            }
            if (TERMS == 3) {
#pragma unroll
                for (int p = 0; p < 2; p++) {
                    if (TRANSB) ldm4(bl[p], coff + bxk[p][ks] + 8192u);
                    else        ldm4t(bl[p], coff + bxk[p][ks] + 8192u);
                }
            }
            // interleave next-stage loads between fragment loads and MMAs
            if (more) { if (ks == 0) cpa_A(kt + 2, loff); else cpa_B(kt + 2, loff); }

#pragma unroll
            for (int mt = 0; mt < 4; mt++)
#pragma unroll
                for (int nt = 0; nt < 4; nt++)
                    mma16(acc[mt][nt], ah[mt], &bh[nt >> 1][(nt & 1) * 2]);
            if (TERMS == 3) {
#pragma unroll
                for (int mt = 0; mt < 4; mt++)
#pragma unroll
                    for (int nt = 0; nt < 4; nt++)
                        mma16(acc[mt][nt], ah[mt], &bl[nt >> 1][(nt & 1) * 2]);
            }

            unsigned al[4][4];
#pragma unroll
            for (int mt = 0; mt < 4; mt++) ldm4(al[mt], coff + axk[mt][ks] + 8192u);
#pragma unroll
            for (int mt = 0; mt < 4; mt++)
#pragma unroll
                for (int nt = 0; nt < 4; nt++)
                    mma16(acc[mt][nt], al[mt], &bh[nt >> 1][(nt & 1) * 2]);
        }

        asm volatile("cp.async.commit_group;" ::: "memory");
        coff = (coff == topoff) ? stiles : coff + STG;
        loff = (loff == topoff) ? stiles : loff + STG;
    }

    // ---- epilogue ----
#pragma unroll
    for (int mt = 0; mt < 4; mt++) {
        int m = m0 + aBase + mt * 16 + g;
#pragma unroll
        for (int nt = 0; nt < 4; nt++) {
            int n = n0 + bBase + nt * 8 + tg * 2;
            float b0 = 0.f, b1 = 0.f;
            if (BIAS) { b0 = bias[n]; b1 = bias[n + 1]; }
            float v00 = acc[mt][nt][0] * scale + b0;
            float v01 = acc[mt][nt][1] * scale + b1;
            float v10 = acc[mt][nt][2] * scale + b0;
            float v11 = acc[mt][nt][3] * scale + b1;
            if (SPLITOUT) {
                unsigned h, l;
                split2(v00, v01, h, l);
                *(unsigned*)&Ch[(size_t)m * Nld + n] = h;
                *(unsigned*)&Cl[(size_t)m * Nld + n] = l;
                split2(v10, v11, h, l);
                *(unsigned*)&Ch[(size_t)(m + 8) * Nld + n] = h;
                *(unsigned*)&Cl[(size_t)(m + 8) * Nld + n] = l;
            } else {
                *(float2*)&C[(size_t)m * Nld + n] = make_float2(v00, v01);
                *(float2*)&C[(size_t)(m + 8) * Nld + n] = make_float2(v10, v11);
            }
        }
    }
}

// ---------------------------------------------------------------------------
// Per-row exact top-k threshold (4-pass MSB radix select, warp-parallel scan)
// + masked softmax. One block (256 threads) per row. Masked entries -> 0.
// ---------------------------------------------------------------------------
__device__ __forceinline__ unsigned f2u(float f) {
    unsigned b = __float_as_uint(f);
    return (b & 0x80000000u) ? ~b : (b | 0x80000000u);
}
__device__ __forceinline__ float u2f(unsigned u) {
    unsigned b = (u & 0x80000000u) ? (u & 0x7fffffffu) : ~u;
    return __uint_as_float(b);
}

__global__ void __launch_bounds__(256) topk_softmax(const float* __restrict__ S,
                                                    __half* __restrict__ Ph,
                                                    __half* __restrict__ Pl) {
    const size_t row = blockIdx.x;
    const float* p = S + row * NN;
    const int tid = threadIdx.x;

    __shared__ int hist[256];
    __shared__ int s_digit, s_rem;
    __shared__ unsigned s_warpk[8];
    __shared__ float s_warpf[8];
    __shared__ float s_sum;

    float val[8];
    unsigned key[8];
    {
        float4 v0 = *(const float4*)&p[tid * 4];
        float4 v1 = *(const float4*)&p[1024 + tid * 4];
        val[0] = v0.x; val[1] = v0.y; val[2] = v0.z; val[3] = v0.w;
        val[4] = v1.x; val[5] = v1.y; val[6] = v1.z; val[7] = v1.w;
    }
    unsigned lmax = 0;
#pragma unroll
    for (int i = 0; i < 8; i++) {
        key[i] = f2u(val[i]);
        lmax = max(lmax, key[i]);
    }

    lmax = __reduce_max_sync(0xffffffffu, lmax);
    if ((tid & 31) == 0) s_warpk[tid >> 5] = lmax;
    __syncthreads();
    if (tid == 0) {
        unsigned m = s_warpk[0];
#pragma unroll
        for (int w = 1; w < 8; w++) m = max(m, s_warpk[w]);
        s_warpk[0] = m;
        s_rem = KKEEP;
    }

    unsigned prefix = 0, pmask = 0;
    for (int shift = 24; shift >= 0; shift -= 8) {
        hist[tid] = 0;
        __syncthreads();
#pragma unroll
        for (int i = 0; i < 8; i++)
            if ((key[i] & pmask) == prefix)
                atomicAdd(&hist[(key[i] >> shift) & 255], 1);
        __syncthreads();
        if (tid < 32) {
            const int base = tid * 8;
            int c[8], tot = 0;
#pragma unroll
            for (int j = 0; j < 8; j++) { c[j] = hist[base + j]; tot += c[j]; }
            int incl = tot;
#pragma unroll
            for (int o = 1; o < 32; o <<= 1) {
                int u = __shfl_down_sync(0xffffffffu, incl, o);
                if (tid + o < 32) incl += u;
            }
            const int excl = incl - tot;       // sum over digits > base+7
            const int remk = s_rem;
            if (excl < remk && excl + tot >= remk) {
                int cum = excl, j = 7;
#pragma unroll
                for (; j > 0; j--) {
                    cum += c[j];
                    if (cum >= remk) break;
                }
                if (cum < remk) cum += c[0];   // j==0 fallthrough
                s_digit = base + j;
                s_rem = remk - (cum - c[j]);
            }
        }
        __syncthreads();
        prefix |= ((unsigned)s_digit) << shift;
        pmask |= 0xFFu << shift;
    }
    const unsigned thr = prefix;
    const float mval = u2f(s_warpk[0]);

    float e[8];
    float lsum = 0.f;
#pragma unroll
    for (int i = 0; i < 8; i++) {
        if (key[i] >= thr) {
            e[i] = __expf(val[i] - mval);
            lsum += e[i];
        } else {
            e[i] = 0.f;
        }
    }
#pragma unroll
    for (int o = 16; o > 0; o >>= 1) lsum += __shfl_down_sync(0xffffffffu, lsum, o);
    if ((tid & 31) == 0) s_warpf[tid >> 5] = lsum;
    __syncthreads();
    if (tid == 0) {
        float s = 0.f;
#pragma unroll
        for (int w = 0; w < 8; w++) s += s_warpf[w];
        s_sum = s;
    }
    __syncthreads();
    const float inv = 1.0f / s_sum;

    const size_t ob = row * NN + tid * 4;
    {
        unsigned h0, l0, h1, l1;
        split2(e[0] * inv, e[1] * inv, h0, l0);
        split2(e[2] * inv, e[3] * inv, h1, l1);
        *(uint2*)&Ph[ob] = make_uint2(h0, h1);
        *(uint2*)&Pl[ob] = make_uint2(l0, l1);
        split2(e[4] * inv, e[5] * inv, h0, l0);
        split2(e[6] * inv, e[7] * inv, h1, l1);
        *(uint2*)&Ph[ob + 1024] = make_uint2(h0, h1);
        *(uint2*)&Pl[ob + 1024] = make_uint2(l0, l1);
    }
}

// ---------------------------------------------------------------------------
// Launch
// ---------------------------------------------------------------------------
extern "C" void kernel_launch(void* const* d_in, const int* in_sizes, int n_in,
                              void* d_out, int out_size) {
    const float* x  = (const float*)d_in[0];
    const float* Wq = (const float*)d_in[1];
    const float* bq = (const float*)d_in[2];
    const float* Wk = (const float*)d_in[3];
    const float* bk = (const float*)d_in[4];
    const float* Wv = (const float*)d_in[5];
    const float* bv = (const float*)d_in[6];
    float* out = (float*)d_out;

    __half *xh, *xl, *Wqh, *Wql, *Wkh, *Wkl, *Wvh, *Wvl;
    __half *Qh, *Ql, *Kh, *Kl, *Vh, *Vl, *Ph, *Pl;
    float* S;
    cudaGetSymbolAddress((void**)&xh, g_xh);
    cudaGetSymbolAddress((void**)&xl, g_xl);
    cudaGetSymbolAddress((void**)&Wqh, g_Wqh);
    cudaGetSymbolAddress((void**)&Wql, g_Wql);
    cudaGetSymbolAddress((void**)&Wkh, g_Wkh);
    cudaGetSymbolAddress((void**)&Wkl, g_Wkl);
    cudaGetSymbolAddress((void**)&Wvh, g_Wvh);
    cudaGetSymbolAddress((void**)&Wvl, g_Wvl);
    cudaGetSymbolAddress((void**)&Qh, g_Qh);
    cudaGetSymbolAddress((void**)&Ql, g_Ql);
    cudaGetSymbolAddress((void**)&Kh, g_Kh);
    cudaGetSymbolAddress((void**)&Kl, g_Kl);
    cudaGetSymbolAddress((void**)&Vh, g_Vh);
    cudaGetSymbolAddress((void**)&Vl, g_Vl);
    cudaGetSymbolAddress((void**)&Ph, g_Ph);
    cudaGetSymbolAddress((void**)&Pl, g_Pl);
    cudaGetSymbolAddress((void**)&S, g_S);

    const int SM3 = 3 * 32768;
    const int SM2 = 3 * 24576;
    cudaFuncSetAttribute(tc_gemm<true, true, true, 3>,
                         cudaFuncAttributeMaxDynamicSharedMemorySize, SM3);
    cudaFuncSetAttribute(tc_gemm<true, true, true, 2>,
                         cudaFuncAttributeMaxDynamicSharedMemorySize, SM2);
    cudaFuncSetAttribute(tc_gemm<true, false, false, 3>,
                         cudaFuncAttributeMaxDynamicSharedMemorySize, SM3);
    cudaFuncSetAttribute(tc_gemm<false, false, false, 2>,
                         cudaFuncAttributeMaxDynamicSharedMemorySize, SM2);

    // prep: split x and weights
    int n4x = BB * NN * CC / 4;
    split_planes<<<n4x / 256, 256>>>(x, xh, xl, n4x);
    int n4w = CC * CC / 4;
    split_planes<<<n4w / 256, 256>>>(Wq, Wqh, Wql, n4w);
    split_planes<<<n4w / 256, 256>>>(Wk, Wkh, Wkl, n4w);
    split_planes<<<n4w / 256, 256>>>(Wv, Wvh, Wvl, n4w);

    dim3 thr(256);

    // Q, K projections: 3-term (feed top-k logits)
    dim3 gqkv(CC / 128, (BB * NN) / 128, 1);
    tc_gemm<true, true, true, 3><<<gqkv, thr, SM3>>>(
        xh, xl, Wqh, Wql, nullptr, Qh, Ql, bq, CC, CC, CC, CC, 0, 0, 0, 1.0f);
    tc_gemm<true, true, true, 3><<<gqkv, thr, SM3>>>(
        xh, xl, Wkh, Wkl, nullptr, Kh, Kl, bk, CC, CC, CC, CC, 0, 0, 0, 1.0f);
    // V projection: 2-term (smooth linear error path)
    tc_gemm<true, true, true, 2><<<gqkv, thr, SM2>>>(
        xh, xl, Wvh, Wvh, nullptr, Vh, Vl, bv, CC, CC, CC, CC, 0, 0, 0, 1.0f);

    // S = Q K^T / sqrt(C): 3-term (top-k boundary accuracy)
    dim3 gs(NN / 128, NN / 128, BB);
    tc_gemm<true, false, false, 3><<<gs, thr, SM3>>>(
        Qh, Ql, Kh, Kl, S, nullptr, nullptr, nullptr, NN, CC, CC, CC,
        (long long)NN * CC, (long long)NN * CC, (long long)NN * NN, 0.03125f);

    // exact top-k + softmax -> P split planes
    topk_softmax<<<BB * NN, 256>>>(S, Ph, Pl);

    // O = P V: 2-term (P split, V hi-only)
    dim3 go(CC / 128, NN / 128, BB);
    tc_gemm<false, false, false, 2><<<go, thr, SM2>>>(
        Ph, Pl, Vh, Vh, out, nullptr, nullptr, nullptr, CC, NN, CC, NN,
        (long long)NN * NN, (long long)NN * CC, (long long)NN * CC, 1.0f);
}

// round 15
// speedup vs baseline: 1.8991x; 1.1497x over previous
#include <cuda_runtime.h>
#include <cuda_fp16.h>
#include <cstdint>

// Problem constants
#define BB 8
#define NN 2048
#define CC 1024
#define KKEEP 1638

// Scratch (allocation-free rule: __device__ globals)
__device__ __half g_xh[BB * NN * CC], g_xl[BB * NN * CC];
__device__ __half g_Wqh[CC * CC], g_Wql[CC * CC];
__device__ __half g_Wkh[CC * CC], g_Wkl[CC * CC];
__device__ __half g_Wvh[CC * CC], g_Wvl[CC * CC];
__device__ __half g_Qh[BB * NN * CC];
__device__ __half g_Kh[BB * NN * CC];
__device__ __half g_Vh[BB * NN * CC];
__device__ float g_Qf[BB * NN * CC];     // fp32 Q for band-exact recompute
__device__ float g_Kf[BB * NN * CC];     // fp32 K
__device__ float g_S[(size_t)BB * NN * NN];
__device__ __half g_Ph[(size_t)BB * NN * NN], g_Pl[(size_t)BB * NN * NN];

// ---------------------------------------------------------------------------
// helpers
// ---------------------------------------------------------------------------
__device__ __forceinline__ void split2(float v0, float v1, unsigned& hi, unsigned& lo) {
    __half2 h = __floats2half2_rn(v0, v1);
    float2 hf = __half22float2(h);
    __half2 l = __floats2half2_rn(v0 - hf.x, v1 - hf.y);
    hi = *reinterpret_cast<unsigned*>(&h);
    lo = *reinterpret_cast<unsigned*>(&l);
}
__device__ __forceinline__ unsigned pack_h2(float v0, float v1) {
    __half2 h = __floats2half2_rn(v0, v1);
    return *reinterpret_cast<unsigned*>(&h);
}

__device__ __forceinline__ void mma16(float* c, const unsigned* a, const unsigned* b) {
    asm volatile(
        "mma.sync.aligned.m16n8k16.row.col.f32.f16.f16.f32 "
        "{%0,%1,%2,%3}, {%4,%5,%6,%7}, {%8,%9}, {%0,%1,%2,%3};"
        : "+f"(c[0]), "+f"(c[1]), "+f"(c[2]), "+f"(c[3])
        : "r"(a[0]), "r"(a[1]), "r"(a[2]), "r"(a[3]), "r"(b[0]), "r"(b[1]));
}
__device__ __forceinline__ void ldm4(unsigned* r, unsigned addr) {
    asm volatile("ldmatrix.sync.aligned.m8n8.x4.shared.b16 {%0,%1,%2,%3}, [%4];"
                 : "=r"(r[0]), "=r"(r[1]), "=r"(r[2]), "=r"(r[3]) : "r"(addr));
}
__device__ __forceinline__ void ldm4t(unsigned* r, unsigned addr) {
    asm volatile("ldmatrix.sync.aligned.m8n8.x4.trans.shared.b16 {%0,%1,%2,%3}, [%4];"
                 : "=r"(r[0]), "=r"(r[1]), "=r"(r[2]), "=r"(r[3]) : "r"(addr));
}
__device__ __forceinline__ void cpa(unsigned s, const void* g) {
    asm volatile("cp.async.cg.shared.global [%0], [%1], 16;" :: "r"(s), "l"(g));
}

// ---------------------------------------------------------------------------
// prep: split fp32 array into fp16 hi/lo planes
// ---------------------------------------------------------------------------
__global__ void split_planes(const float* __restrict__ src,
                             __half* __restrict__ h,
                             __half* __restrict__ l, int n4) {
    int i = blockIdx.x * blockDim.x + threadIdx.x;
    if (i < n4) {
        float4 v = ((const float4*)src)[i];
        unsigned h0, l0, h1, l1;
        split2(v.x, v.y, h0, l0);
        split2(v.z, v.w, h1, l1);
        ((uint2*)h)[i] = make_uint2(h0, h1);
        ((uint2*)l)[i] = make_uint2(l0, l1);
    }
}

// ---------------------------------------------------------------------------
// GEMM: pre-split fp16 planes; cp.async 3-stage; ldmatrix + mma.
// CTA tile 128x128, K_tile=32, 256 threads, 8 warps (2x4) each 64x32.
//   TERMS: 3 = ah*bh+ah*bl+al*bh; 2 = ah*bh+al*bh; 1 = ah*bh
//   OUTMODE: 0 = fp32 C; 1 = fp16 hi-plane Ch; 2 = fp32 C AND hi-plane Ch
//   TRANSB: true -> B planes [N][K] (NT); false -> [K][N] (NN, ldmatrix.trans)
// smem stage: AH(8K) [AL(8K) if TERMS>=2] BH(8K) [BL(8K) if TERMS==3]
// ---------------------------------------------------------------------------
template <bool TRANSB, bool BIAS, int OUTMODE, int TERMS>
__global__ void __launch_bounds__(256, 2)
tc_gemm(const __half* __restrict__ Ah, const __half* __restrict__ Al,
        const __half* __restrict__ Bh, const __half* __restrict__ Bl,
        float* __restrict__ C, __half* __restrict__ Ch,
        const float* __restrict__ bias,
        int Nld, int lda, int ldb, int K,
        long long sA, long long sB, long long sC, float scale) {
    constexpr unsigned STG = (TERMS == 3) ? 32768u : (TERMS == 2) ? 24576u : 16384u;
    constexpr unsigned BOFF = (TERMS >= 2) ? 16384u : 8192u;
    extern __shared__ __align__(16) unsigned char dsm[];
    const unsigned stiles = (unsigned)__cvta_generic_to_shared(dsm);

    Ah += (size_t)blockIdx.z * sA;
    if (TERMS >= 2) Al += (size_t)blockIdx.z * sA;
    Bh += (size_t)blockIdx.z * sB;
    if (TERMS == 3) Bl += (size_t)blockIdx.z * sB;
    if (OUTMODE != 1) C += (size_t)blockIdx.z * sC;
    if (OUTMODE >= 1) Ch += (size_t)blockIdx.z * sC;

    const int t = threadIdx.x;
    const int lane = t & 31;
    const int warp = t >> 5;
    const int wm = warp & 1;
    const int wn = warp >> 1;
    const int g = lane >> 2;
    const int tg = lane & 3;

    const int m0 = blockIdx.y * 128;
    const int n0 = blockIdx.x * 128;
    const int aBase = wm * 64;
    const int bBase = wn * 32;

    float acc[4][4][4];
#pragma unroll
    for (int i = 0; i < 4; i++)
#pragma unroll
        for (int j = 0; j < 4; j++)
#pragma unroll
            for (int r = 0; r < 4; r++) acc[i][j][r] = 0.f;

    const int NK = K / 32;

    // ---- per-thread cp.async src/dst, computed once ----
    unsigned soA[2], soB[2];
    size_t goA[2], goB[2];
#pragma unroll
    for (int p = 0; p < 2; p++) {
        int idx = t + p * 256;
        {
            int r = idx >> 2, c = idx & 3;
            soA[p] = (unsigned)(r * 64 + ((c ^ ((r >> 1) & 3)) << 4));
            goA[p] = (size_t)(m0 + r) * lda + c * 8;
        }
        if (TRANSB) {
            int r = idx >> 2, c = idx & 3;
            soB[p] = BOFF + (unsigned)(r * 64 + ((c ^ ((r >> 1) & 3)) << 4));
            goB[p] = (size_t)(n0 + r) * ldb + c * 8;
        } else {
            int r = idx >> 4, c = idx & 15;
            soB[p] = BOFF + (unsigned)(r * 256 + ((c ^ (r & 7)) << 4));
            goB[p] = (size_t)r * ldb + n0 + c * 8;
        }
    }

    auto cpa_A = [&](int kt, unsigned off) {
        const size_t kadd = (size_t)kt * 32;
#pragma unroll
        for (int p = 0; p < 2; p++) {
            cpa(off + soA[p], Ah + goA[p] + kadd);
            if (TERMS >= 2) cpa(off + soA[p] + 8192u, Al + goA[p] + kadd);
        }
    };
    auto cpa_B = [&](int kt, unsigned off) {
        const size_t kadd = TRANSB ? (size_t)kt * 32 : (size_t)kt * 32 * ldb;
#pragma unroll
        for (int p = 0; p < 2; p++) {
            cpa(off + soB[p], Bh + goB[p] + kadd);
            if (TERMS == 3) cpa(off + soB[p] + 8192u, Bl + goB[p] + kadd);
        }
    };

    // ---- per-thread ldmatrix offsets (relative to stage base) ----
    unsigned axk[4][2];
#pragma unroll
    for (int mt = 0; mt < 4; mt++) {
        int ar = aBase + mt * 16 + (lane & 15);
        int rsw = (ar >> 1) & 3;
        int c0 = lane >> 4;
        axk[mt][0] = (unsigned)(ar * 64 + ((c0 ^ rsw) << 4));
        axk[mt][1] = (unsigned)(ar * 64 + (((c0 + 2) ^ rsw) << 4));
    }
    unsigned bxk[2][2];
    if (TRANSB) {
#pragma unroll
        for (int p = 0; p < 2; p++) {
            int br = bBase + p * 16 + (lane & 7) + (lane >> 4) * 8;
            int rsw = (br >> 1) & 3;
            int c0 = (lane >> 3) & 1;
            bxk[p][0] = BOFF + (unsigned)(br * 64 + ((c0 ^ rsw) << 4));
            bxk[p][1] = BOFF + (unsigned)(br * 64 + (((c0 + 2) ^ rsw) << 4));
        }
    } else {
        int kr = (lane & 7) + ((lane >> 3) & 1) * 8;
#pragma unroll
        for (int p = 0; p < 2; p++) {
            int c = bBase / 8 + (lane >> 4) + 2 * p;
            unsigned b0 = BOFF + (unsigned)(kr * 256 + ((c ^ (kr & 7)) << 4));
            bxk[p][0] = b0;
            bxk[p][1] = b0 + 4096u;   // +16 k-rows
        }
    }

    // ---- prologue: stages 0 and 1 ----
    cpa_A(0, stiles);
    cpa_B(0, stiles);
    asm volatile("cp.async.commit_group;" ::: "memory");
    cpa_A(1, stiles + STG);
    cpa_B(1, stiles + STG);
    asm volatile("cp.async.commit_group;" ::: "memory");

    unsigned coff = stiles;                 // compute stage base
    unsigned loff = stiles + 2 * STG;       // load stage base (kt+2)
    const unsigned topoff = stiles + 2 * STG;

    for (int kt = 0; kt < NK; kt++) {
        asm volatile("cp.async.wait_group 1;" ::: "memory");
        __syncthreads();
        const bool more = (kt + 2) < NK;

#pragma unroll
        for (int ks = 0; ks < 2; ks++) {
            unsigned ah[4][4], bh[2][4], bl[2][4];
#pragma unroll
            for (int mt = 0; mt < 4; mt++) ldm4(ah[mt], coff + axk[mt][ks]);
#pragma unroll
            for (int p = 0; p < 2; p++) {
                if (TRANSB) ldm4(bh[p], coff + bxk[p][ks]);
                else        ldm4t(bh[p], coff + bxk[p][ks]);
            }
            if (TERMS == 3) {
#pragma unroll
                for (int p = 0; p < 2; p++) {
                    if (TRANSB) ldm4(bl[p], coff + bxk[p][ks] + 8192u);
                    else        ldm4t(bl[p], coff + bxk[p][ks] + 8192u);
                }
            }
            if (more) { if (ks == 0) cpa_A(kt + 2, loff); else cpa_B(kt + 2, loff); }

#pragma unroll
            for (int mt = 0; mt < 4; mt++)
#pragma unroll
                for (int nt = 0; nt < 4; nt++)
                    mma16(acc[mt][nt], ah[mt], &bh[nt >> 1][(nt & 1) * 2]);
            if (TERMS == 3) {
#pragma unroll
                for (int mt = 0; mt < 4; mt++)
#pragma unroll
                    for (int nt = 0; nt < 4; nt++)
                        mma16(acc[mt][nt], ah[mt], &bl[nt >> 1][(nt & 1) * 2]);
            }
            if (TERMS >= 2) {
                unsigned al[4][4];
#pragma unroll
                for (int mt = 0; mt < 4; mt++) ldm4(al[mt], coff + axk[mt][ks] + 8192u);
#pragma unroll
                for (int mt = 0; mt < 4; mt++)
#pragma unroll
                    for (int nt = 0; nt < 4; nt++)
                        mma16(acc[mt][nt], al[mt], &bh[nt >> 1][(nt & 1) * 2]);
            }
        }

        asm volatile("cp.async.commit_group;" ::: "memory");
        coff = (coff == topoff) ? stiles : coff + STG;
        loff = (loff == topoff) ? stiles : loff + STG;
    }

    // ---- epilogue ----
#pragma unroll
    for (int mt = 0; mt < 4; mt++) {
        int m = m0 + aBase + mt * 16 + g;
#pragma unroll
        for (int nt = 0; nt < 4; nt++) {
            int n = n0 + bBase + nt * 8 + tg * 2;
            float b0 = 0.f, b1 = 0.f;
            if (BIAS) { b0 = bias[n]; b1 = bias[n + 1]; }
            float v00 = acc[mt][nt][0] * scale + b0;
            float v01 = acc[mt][nt][1] * scale + b1;
            float v10 = acc[mt][nt][2] * scale + b0;
            float v11 = acc[mt][nt][3] * scale + b1;
            if (OUTMODE != 1) {
                *(float2*)&C[(size_t)m * Nld + n] = make_float2(v00, v01);
                *(float2*)&C[(size_t)(m + 8) * Nld + n] = make_float2(v10, v11);
            }
            if (OUTMODE >= 1) {
                *(unsigned*)&Ch[(size_t)m * Nld + n] = pack_h2(v00, v01);
                *(unsigned*)&Ch[(size_t)(m + 8) * Nld + n] = pack_h2(v10, v11);
            }
        }
    }
}

// ---------------------------------------------------------------------------
// Band-exact top-k + masked softmax.
// S̃ is 1-term fp16 approx (err << BAND). Radix-select τ̃ = 1638th of S̃.
// S̃ > τ̃+BAND: certainly kept; S̃ < τ̃−BAND: certainly dropped; band elements
// resolved by exact fp32 dot(Q[row], K[col]) ranking. Softmax on S̃ values.
// ---------------------------------------------------------------------------
#define BAND 1.5e-3f

__device__ __forceinline__ unsigned f2u(float f) {
    unsigned b = __float_as_uint(f);
    return (b & 0x80000000u) ? ~b : (b | 0x80000000u);
}
__device__ __forceinline__ float u2f(unsigned u) {
    unsigned b = (u & 0x80000000u) ? (u & 0x7fffffffu) : ~u;
    return __uint_as_float(b);
}

__global__ void __launch_bounds__(256) topk_softmax(const float* __restrict__ S,
                                                    const float* __restrict__ Qf,
                                                    const float* __restrict__ Kf,
                                                    __half* __restrict__ Ph,
                                                    __half* __restrict__ Pl) {
    const int row = blockIdx.x;          // [0, BB*NN)
    const int batch = row >> 11;
    const float* p = S + (size_t)row * NN;
    const int tid = threadIdx.x;

    __shared__ float Qs[CC];
    __shared__ int hist[256];
    __shared__ int s_digit, s_rem;
    __shared__ unsigned s_warpk[8];
    __shared__ float s_warpf[8];
    __shared__ float s_sum;
    __shared__ int s_nin, s_bandcnt;
    __shared__ short s_bandidx[64];
    __shared__ float s_bandval[64];
    __shared__ unsigned char s_bandkeep[64];

    // cache Q row (fp32) for band recompute
#pragma unroll
    for (int i = 0; i < CC / 256; i++)
        Qs[tid + i * 256] = Qf[(size_t)row * CC + tid + i * 256];

    // load S̃ row (vectorized)
    float val[8];
    unsigned key[8];
    {
        float4 v0 = *(const float4*)&p[tid * 4];
        float4 v1 = *(const float4*)&p[1024 + tid * 4];
        val[0] = v0.x; val[1] = v0.y; val[2] = v0.z; val[3] = v0.w;
        val[4] = v1.x; val[5] = v1.y; val[6] = v1.z; val[7] = v1.w;
    }
    unsigned lmax = 0;
#pragma unroll
    for (int i = 0; i < 8; i++) {
        key[i] = f2u(val[i]);
        lmax = max(lmax, key[i]);
    }

    lmax = __reduce_max_sync(0xffffffffu, lmax);
    if ((tid & 31) == 0) s_warpk[tid >> 5] = lmax;
    __syncthreads();
    if (tid == 0) {
        unsigned m = s_warpk[0];
#pragma unroll
        for (int w = 1; w < 8; w++) m = max(m, s_warpk[w]);
        s_warpk[0] = m;
        s_rem = KKEEP;
        s_nin = 0;
        s_bandcnt = 0;
    }

    // radix select τ̃ = 1638th largest of S̃ (4 passes, warp-scan)
    unsigned prefix = 0, pmask = 0;
    for (int shift = 24; shift >= 0; shift -= 8) {
        hist[tid] = 0;
        __syncthreads();
#pragma unroll
        for (int i = 0; i < 8; i++)
            if ((key[i] & pmask) == prefix)
                atomicAdd(&hist[(key[i] >> shift) & 255], 1);
        __syncthreads();
        if (tid < 32) {
            const int base = tid * 8;
            int c[8], tot = 0;
#pragma unroll
            for (int j = 0; j < 8; j++) { c[j] = hist[base + j]; tot += c[j]; }
            int incl = tot;
#pragma unroll
            for (int o = 1; o < 32; o <<= 1) {
                int u = __shfl_down_sync(0xffffffffu, incl, o);
                if (tid + o < 32) incl += u;
            }
            const int excl = incl - tot;
            const int remk = s_rem;
            if (excl < remk && excl + tot >= remk) {
                int cum = excl, j = 7;
#pragma unroll
                for (; j > 0; j--) {
                    cum += c[j];
                    if (cum >= remk) break;
                }
                if (cum < remk) cum += c[0];
                s_digit = base + j;
                s_rem = remk - (cum - c[j]);
            }
        }
        __syncthreads();
        prefix |= ((unsigned)s_digit) << shift;
        pmask |= 0xFFu << shift;
    }
    const float tau = u2f(prefix);

    // classify: definitely-in / band / out
    int bandpos[8];
    int ninLocal = 0;
#pragma unroll
    for (int i = 0; i < 8; i++) {
        bandpos[i] = -1;
        if (val[i] > tau + BAND) {
            ninLocal++;
        } else if (val[i] >= tau - BAND) {
            int pos = atomicAdd(&s_bandcnt, 1);
            if (pos < 64) {
                int col = (i < 4) ? (tid * 4 + i) : (1024 + tid * 4 + (i - 4));
                s_bandidx[pos] = (short)col;
                bandpos[i] = pos;
            }
        }
    }
#pragma unroll
    for (int o = 16; o > 0; o >>= 1) ninLocal += __shfl_down_sync(0xffffffffu, ninLocal, o);
    if ((tid & 31) == 0) atomicAdd(&s_nin, ninLocal);
    __syncthreads();

    const int bandcnt = min(s_bandcnt, 64);
    const int need = KKEEP - s_nin;

    // exact fp32 dots for band elements (one warp per element, round-robin)
    {
        const int w = tid >> 5, l = tid & 31;
        for (int b = w; b < bandcnt; b += 8) {
            const float* kr = Kf + ((size_t)(batch * NN + s_bandidx[b])) * CC;
            float sum = 0.f;
#pragma unroll 8
            for (int k = l; k < CC; k += 32) sum += Qs[k] * kr[k];
#pragma unroll
            for (int o = 16; o > 0; o >>= 1) sum += __shfl_down_sync(0xffffffffu, sum, o);
            if (l == 0) s_bandval[b] = sum;
        }
    }
    __syncthreads();

    // rank band by exact value; keep top-'need'
    if (tid < bandcnt) {
        const float v = s_bandval[tid];
        int r = 0;
        for (int j = 0; j < bandcnt; j++) {
            float u = s_bandval[j];
            if (u > v || (u == v && j < tid)) r++;
        }
        s_bandkeep[tid] = (r < need) ? 1 : 0;
    }
    __syncthreads();

    // masked softmax on S̃ values
    const float mval = u2f(s_warpk[0]);
    float e[8];
    float lsum = 0.f;
#pragma unroll
    for (int i = 0; i < 8; i++) {
        bool keep;
        if (val[i] > tau + BAND) keep = true;
        else if (val[i] >= tau - BAND)
            keep = (bandpos[i] >= 0) ? (s_bandkeep[bandpos[i]] != 0) : (val[i] >= tau);
        else keep = false;
        e[i] = keep ? __expf(val[i] - mval) : 0.f;
        lsum += e[i];
    }
#pragma unroll
    for (int o = 16; o > 0; o >>= 1) lsum += __shfl_down_sync(0xffffffffu, lsum, o);
    if ((tid & 31) == 0) s_warpf[tid >> 5] = lsum;
    __syncthreads();
    if (tid == 0) {
        float s = 0.f;
#pragma unroll
        for (int w = 0; w < 8; w++) s += s_warpf[w];
        s_sum = s;
    }
    __syncthreads();
    const float inv = 1.0f / s_sum;

    const size_t ob = (size_t)row * NN + tid * 4;
    {
        unsigned h0, l0, h1, l1;
        split2(e[0] * inv, e[1] * inv, h0, l0);
        split2(e[2] * inv, e[3] * inv, h1, l1);
        *(uint2*)&Ph[ob] = make_uint2(h0, h1);
        *(uint2*)&Pl[ob] = make_uint2(l0, l1);
        split2(e[4] * inv, e[5] * inv, h0, l0);
        split2(e[6] * inv, e[7] * inv, h1, l1);
        *(uint2*)&Ph[ob + 1024] = make_uint2(h0, h1);
        *(uint2*)&Pl[ob + 1024] = make_uint2(l0, l1);
    }
}

// ---------------------------------------------------------------------------
// Launch
// ---------------------------------------------------------------------------
extern "C" void kernel_launch(void* const* d_in, const int* in_sizes, int n_in,
                              void* d_out, int out_size) {
    const float* x  = (const float*)d_in[0];
    const float* Wq = (const float*)d_in[1];
    const float* bq = (const float*)d_in[2];
    const float* Wk = (const float*)d_in[3];
    const float* bk = (const float*)d_in[4];
    const float* Wv = (const float*)d_in[5];
    const float* bv = (const float*)d_in[6];
    float* out = (float*)d_out;

    __half *xh, *xl, *Wqh, *Wql, *Wkh, *Wkl, *Wvh, *Wvl;
    __half *Qh, *Kh, *Vh, *Ph, *Pl;
    float *Qf, *Kf, *S;
    cudaGetSymbolAddress((void**)&xh, g_xh);
    cudaGetSymbolAddress((void**)&xl, g_xl);
    cudaGetSymbolAddress((void**)&Wqh, g_Wqh);
    cudaGetSymbolAddress((void**)&Wql, g_Wql);
    cudaGetSymbolAddress((void**)&Wkh, g_Wkh);
    cudaGetSymbolAddress((void**)&Wkl, g_Wkl);
    cudaGetSymbolAddress((void**)&Wvh, g_Wvh);
    cudaGetSymbolAddress((void**)&Wvl, g_Wvl);
    cudaGetSymbolAddress((void**)&Qh, g_Qh);
    cudaGetSymbolAddress((void**)&Kh, g_Kh);
    cudaGetSymbolAddress((void**)&Vh, g_Vh);
    cudaGetSymbolAddress((void**)&Qf, g_Qf);
    cudaGetSymbolAddress((void**)&Kf, g_Kf);
    cudaGetSymbolAddress((void**)&Ph, g_Ph);
    cudaGetSymbolAddress((void**)&Pl, g_Pl);
    cudaGetSymbolAddress((void**)&S, g_S);

    const int SM3 = 3 * 32768;
    const int SM2 = 3 * 24576;
    const int SM1 = 3 * 16384;
    cudaFuncSetAttribute(tc_gemm<true, true, 2, 3>,
                         cudaFuncAttributeMaxDynamicSharedMemorySize, SM3);
    cudaFuncSetAttribute(tc_gemm<true, true, 1, 2>,
                         cudaFuncAttributeMaxDynamicSharedMemorySize, SM2);
    cudaFuncSetAttribute(tc_gemm<true, false, 0, 1>,
                         cudaFuncAttributeMaxDynamicSharedMemorySize, SM1);
    cudaFuncSetAttribute(tc_gemm<false, false, 0, 2>,
                         cudaFuncAttributeMaxDynamicSharedMemorySize, SM2);

    // prep: split x and weights
    int n4x = BB * NN * CC / 4;
    split_planes<<<n4x / 256, 256>>>(x, xh, xl, n4x);
    int n4w = CC * CC / 4;
    split_planes<<<n4w / 256, 256>>>(Wq, Wqh, Wql, n4w);
    split_planes<<<n4w / 256, 256>>>(Wk, Wkh, Wkl, n4w);
    split_planes<<<n4w / 256, 256>>>(Wv, Wvh, Wvl, n4w);

    dim3 thr(256);

    // Q, K projections: 3-term, output fp32 + hi-plane
    dim3 gqkv(CC / 128, (BB * NN) / 128, 1);
    tc_gemm<true, true, 2, 3><<<gqkv, thr, SM3>>>(
        xh, xl, Wqh, Wql, Qf, Qh, bq, CC, CC, CC, CC, 0, 0, 0, 1.0f);
    tc_gemm<true, true, 2, 3><<<gqkv, thr, SM3>>>(
        xh, xl, Wkh, Wkl, Kf, Kh, bk, CC, CC, CC, CC, 0, 0, 0, 1.0f);
    // V projection: 2-term, hi-plane only (PV uses Vh only)
    tc_gemm<true, true, 1, 2><<<gqkv, thr, SM2>>>(
        xh, xl, Wvh, Wvh, nullptr, Vh, bv, CC, CC, CC, CC, 0, 0, 0, 1.0f);

    // S̃ = Qh Kh^T / sqrt(C): 1-term fp16 (band-exact topk resolves boundary)
    dim3 gs(NN / 128, NN / 128, BB);
    tc_gemm<true, false, 0, 1><<<gs, thr, SM1>>>(
        Qh, Qh, Kh, Kh, S, nullptr, nullptr, NN, CC, CC, CC,
        (long long)NN * CC, (long long)NN * CC, (long long)NN * NN, 0.03125f);

    // band-exact top-k + softmax -> P split planes
    topk_softmax<<<BB * NN, 256>>>(S, Qf, Kf, Ph, Pl);

    // O = P V: 2-term (P split, V hi-only)
    dim3 go(CC / 128, NN / 128, BB);
    tc_gemm<false, false, 0, 2><<<go, thr, SM2>>>(
        Ph, Pl, Vh, Vh, out, nullptr, nullptr, CC, NN, CC, NN,
        (long long)NN * NN, (long long)NN * CC, (long long)NN * CC, 1.0f);
}

// round 16
// speedup vs baseline: 2.2656x; 1.1930x over previous
#include <cuda_runtime.h>
#include <cuda_fp16.h>
#include <cstdint>

// Problem constants
#define BB 8
#define NN 2048
#define CC 1024
#define KKEEP 1638

// Scratch (allocation-free rule: __device__ globals)
__device__ __half g_xh[BB * NN * CC], g_xl[BB * NN * CC];
__device__ __half g_Wqh[CC * CC], g_Wql[CC * CC];
__device__ __half g_Wkh[CC * CC], g_Wkl[CC * CC];
__device__ __half g_Wvh[CC * CC];
__device__ __half g_Qh[BB * NN * CC];
__device__ __half g_Kh[BB * NN * CC];
__device__ __half g_Vh[BB * NN * CC];
__device__ float g_Qf[BB * NN * CC];     // fp32 Q for band-exact recompute
__device__ float g_Kf[BB * NN * CC];     // fp32 K
__device__ float g_S[(size_t)BB * NN * NN];
__device__ __half g_Ph[(size_t)BB * NN * NN];

// ---------------------------------------------------------------------------
// helpers
// ---------------------------------------------------------------------------
__device__ __forceinline__ void split2(float v0, float v1, unsigned& hi, unsigned& lo) {
    __half2 h = __floats2half2_rn(v0, v1);
    float2 hf = __half22float2(h);
    __half2 l = __floats2half2_rn(v0 - hf.x, v1 - hf.y);
    hi = *reinterpret_cast<unsigned*>(&h);
    lo = *reinterpret_cast<unsigned*>(&l);
}
__device__ __forceinline__ unsigned pack_h2(float v0, float v1) {
    __half2 h = __floats2half2_rn(v0, v1);
    return *reinterpret_cast<unsigned*>(&h);
}

__device__ __forceinline__ void mma16(float* c, const unsigned* a, const unsigned* b) {
    asm volatile(
        "mma.sync.aligned.m16n8k16.row.col.f32.f16.f16.f32 "
        "{%0,%1,%2,%3}, {%4,%5,%6,%7}, {%8,%9}, {%0,%1,%2,%3};"
        : "+f"(c[0]), "+f"(c[1]), "+f"(c[2]), "+f"(c[3])
        : "r"(a[0]), "r"(a[1]), "r"(a[2]), "r"(a[3]), "r"(b[0]), "r"(b[1]));
}
__device__ __forceinline__ void ldm4(unsigned* r, unsigned addr) {
    asm volatile("ldmatrix.sync.aligned.m8n8.x4.shared.b16 {%0,%1,%2,%3}, [%4];"
                 : "=r"(r[0]), "=r"(r[1]), "=r"(r[2]), "=r"(r[3]) : "r"(addr));
}
__device__ __forceinline__ void ldm4t(unsigned* r, unsigned addr) {
    asm volatile("ldmatrix.sync.aligned.m8n8.x4.trans.shared.b16 {%0,%1,%2,%3}, [%4];"
                 : "=r"(r[0]), "=r"(r[1]), "=r"(r[2]), "=r"(r[3]) : "r"(addr));
}
__device__ __forceinline__ void cpa(unsigned s, const void* g) {
    asm volatile("cp.async.cg.shared.global [%0], [%1], 16;" :: "r"(s), "l"(g));
}

// ---------------------------------------------------------------------------
// prep: split fp32 array into fp16 hi/lo planes (lo may be null -> hi only)
// ---------------------------------------------------------------------------
__global__ void split_planes(const float* __restrict__ src,
                             __half* __restrict__ h,
                             __half* __restrict__ l, int n4) {
    int i = blockIdx.x * blockDim.x + threadIdx.x;
    if (i < n4) {
        float4 v = ((const float4*)src)[i];
        unsigned h0, l0, h1, l1;
        split2(v.x, v.y, h0, l0);
        split2(v.z, v.w, h1, l1);
        ((uint2*)h)[i] = make_uint2(h0, h1);
        if (l) ((uint2*)l)[i] = make_uint2(l0, l1);
    }
}

// ---------------------------------------------------------------------------
// GEMM: pre-split fp16 planes; cp.async 3-stage; ldmatrix + mma.
// CTA tile 128x128, K_tile=32, 256 threads, 8 warps (2x4) each 64x32.
//   TERMS: 3 = ah*bh+ah*bl+al*bh; 2 = ah*bh+al*bh; 1 = ah*bh
//   OUTMODE: 0 = fp32 C; 1 = fp16 hi-plane Ch; 2 = fp32 C AND hi-plane Ch
//   TRANSB: true -> B planes [N][K] (NT); false -> [K][N] (NN, ldmatrix.trans)
// smem stage: AH(8K) [AL(8K) if TERMS>=2] BH(8K) [BL(8K) if TERMS==3]
// ---------------------------------------------------------------------------
template <bool TRANSB, bool BIAS, int OUTMODE, int TERMS>
__global__ void __launch_bounds__(256, 2)
tc_gemm(const __half* __restrict__ Ah, const __half* __restrict__ Al,
        const __half* __restrict__ Bh, const __half* __restrict__ Bl,
        float* __restrict__ C, __half* __restrict__ Ch,
        const float* __restrict__ bias,
        int Nld, int lda, int ldb, int K,
        long long sA, long long sB, long long sC, float scale) {
    constexpr unsigned STG = (TERMS == 3) ? 32768u : (TERMS == 2) ? 24576u : 16384u;
    constexpr unsigned BOFF = (TERMS >= 2) ? 16384u : 8192u;
    extern __shared__ __align__(16) unsigned char dsm[];
    const unsigned stiles = (unsigned)__cvta_generic_to_shared(dsm);

    Ah += (size_t)blockIdx.z * sA;
    if (TERMS >= 2) Al += (size_t)blockIdx.z * sA;
    Bh += (size_t)blockIdx.z * sB;
    if (TERMS == 3) Bl += (size_t)blockIdx.z * sB;
    if (OUTMODE != 1) C += (size_t)blockIdx.z * sC;
    if (OUTMODE >= 1) Ch += (size_t)blockIdx.z * sC;

    const int t = threadIdx.x;
    const int lane = t & 31;
    const int warp = t >> 5;
    const int wm = warp & 1;
    const int wn = warp >> 1;
    const int g = lane >> 2;
    const int tg = lane & 3;

    const int m0 = blockIdx.y * 128;
    const int n0 = blockIdx.x * 128;
    const int aBase = wm * 64;
    const int bBase = wn * 32;

    float acc[4][4][4];
#pragma unroll
    for (int i = 0; i < 4; i++)
#pragma unroll
        for (int j = 0; j < 4; j++)
#pragma unroll
            for (int r = 0; r < 4; r++) acc[i][j][r] = 0.f;

    const int NK = K / 32;

    // ---- per-thread cp.async src/dst, computed once ----
    unsigned soA[2], soB[2];
    size_t goA[2], goB[2];
#pragma unroll
    for (int p = 0; p < 2; p++) {
        int idx = t + p * 256;
        {
            int r = idx >> 2, c = idx & 3;
            soA[p] = (unsigned)(r * 64 + ((c ^ ((r >> 1) & 3)) << 4));
            goA[p] = (size_t)(m0 + r) * lda + c * 8;
        }
        if (TRANSB) {
            int r = idx >> 2, c = idx & 3;
            soB[p] = BOFF + (unsigned)(r * 64 + ((c ^ ((r >> 1) & 3)) << 4));
            goB[p] = (size_t)(n0 + r) * ldb + c * 8;
        } else {
            int r = idx >> 4, c = idx & 15;
            soB[p] = BOFF + (unsigned)(r * 256 + ((c ^ (r & 7)) << 4));
            goB[p] = (size_t)r * ldb + n0 + c * 8;
        }
    }

    auto cpa_A = [&](int kt, unsigned off) {
        const size_t kadd = (size_t)kt * 32;
#pragma unroll
        for (int p = 0; p < 2; p++) {
            cpa(off + soA[p], Ah + goA[p] + kadd);
            if (TERMS >= 2) cpa(off + soA[p] + 8192u, Al + goA[p] + kadd);
        }
    };
    auto cpa_B = [&](int kt, unsigned off) {
        const size_t kadd = TRANSB ? (size_t)kt * 32 : (size_t)kt * 32 * ldb;
#pragma unroll
        for (int p = 0; p < 2; p++) {
            cpa(off + soB[p], Bh + goB[p] + kadd);
            if (TERMS == 3) cpa(off + soB[p] + 8192u, Bl + goB[p] + kadd);
        }
    };

    // ---- per-thread ldmatrix offsets (relative to stage base) ----
    unsigned axk[4][2];
#pragma unroll
    for (int mt = 0; mt < 4; mt++) {
        int ar = aBase + mt * 16 + (lane & 15);
        int rsw = (ar >> 1) & 3;
        int c0 = lane >> 4;
        axk[mt][0] = (unsigned)(ar * 64 + ((c0 ^ rsw) << 4));
        axk[mt][1] = (unsigned)(ar * 64 + (((c0 + 2) ^ rsw) << 4));
    }
    unsigned bxk[2][2];
    if (TRANSB) {
#pragma unroll
        for (int p = 0; p < 2; p++) {
            int br = bBase + p * 16 + (lane & 7) + (lane >> 4) * 8;
            int rsw = (br >> 1) & 3;
            int c0 = (lane >> 3) & 1;
            bxk[p][0] = BOFF + (unsigned)(br * 64 + ((c0 ^ rsw) << 4));
            bxk[p][1] = BOFF + (unsigned)(br * 64 + (((c0 + 2) ^ rsw) << 4));
        }
    } else {
        int kr = (lane & 7) + ((lane >> 3) & 1) * 8;
#pragma unroll
        for (int p = 0; p < 2; p++) {
            int c = bBase / 8 + (lane >> 4) + 2 * p;
            unsigned b0 = BOFF + (unsigned)(kr * 256 + ((c ^ (kr & 7)) << 4));
            bxk[p][0] = b0;
            bxk[p][1] = b0 + 4096u;   // +16 k-rows
        }
    }

    // ---- prologue: stages 0 and 1 ----
    cpa_A(0, stiles);
    cpa_B(0, stiles);
    asm volatile("cp.async.commit_group;" ::: "memory");
    cpa_A(1, stiles + STG);
    cpa_B(1, stiles + STG);
    asm volatile("cp.async.commit_group;" ::: "memory");

    unsigned coff = stiles;                 // compute stage base
    unsigned loff = stiles + 2 * STG;       // load stage base (kt+2)
    const unsigned topoff = stiles + 2 * STG;

    for (int kt = 0; kt < NK; kt++) {
        asm volatile("cp.async.wait_group 1;" ::: "memory");
        __syncthreads();
        const bool more = (kt + 2) < NK;

#pragma unroll
        for (int ks = 0; ks < 2; ks++) {
            unsigned ah[4][4], bh[2][4], bl[2][4];
#pragma unroll
            for (int mt = 0; mt < 4; mt++) ldm4(ah[mt], coff + axk[mt][ks]);
#pragma unroll
            for (int p = 0; p < 2; p++) {
                if (TRANSB) ldm4(bh[p], coff + bxk[p][ks]);
                else        ldm4t(bh[p], coff + bxk[p][ks]);
            }
            if (TERMS == 3) {
#pragma unroll
                for (int p = 0; p < 2; p++) {
                    if (TRANSB) ldm4(bl[p], coff + bxk[p][ks] + 8192u);
                    else        ldm4t(bl[p], coff + bxk[p][ks] + 8192u);
                }
            }
            if (more) { if (ks == 0) cpa_A(kt + 2, loff); else cpa_B(kt + 2, loff); }

#pragma unroll
            for (int mt = 0; mt < 4; mt++)
#pragma unroll
                for (int nt = 0; nt < 4; nt++)
                    mma16(acc[mt][nt], ah[mt], &bh[nt >> 1][(nt & 1) * 2]);
            if (TERMS == 3) {
#pragma unroll
                for (int mt = 0; mt < 4; mt++)
#pragma unroll
                    for (int nt = 0; nt < 4; nt++)
                        mma16(acc[mt][nt], ah[mt], &bl[nt >> 1][(nt & 1) * 2]);
            }
            if (TERMS >= 2) {
                unsigned al[4][4];
#pragma unroll
                for (int mt = 0; mt < 4; mt++) ldm4(al[mt], coff + axk[mt][ks] + 8192u);
#pragma unroll
                for (int mt = 0; mt < 4; mt++)
#pragma unroll
                    for (int nt = 0; nt < 4; nt++)
                        mma16(acc[mt][nt], al[mt], &bh[nt >> 1][(nt & 1) * 2]);
            }
        }

        asm volatile("cp.async.commit_group;" ::: "memory");
        coff = (coff == topoff) ? stiles : coff + STG;
        loff = (loff == topoff) ? stiles : loff + STG;
    }

    // ---- epilogue ----
#pragma unroll
    for (int mt = 0; mt < 4; mt++) {
        int m = m0 + aBase + mt * 16 + g;
#pragma unroll
        for (int nt = 0; nt < 4; nt++) {
            int n = n0 + bBase + nt * 8 + tg * 2;
            float b0 = 0.f, b1 = 0.f;
            if (BIAS) { b0 = bias[n]; b1 = bias[n + 1]; }
            float v00 = acc[mt][nt][0] * scale + b0;
            float v01 = acc[mt][nt][1] * scale + b1;
            float v10 = acc[mt][nt][2] * scale + b0;
            float v11 = acc[mt][nt][3] * scale + b1;
            if (OUTMODE != 1) {
                *(float2*)&C[(size_t)m * Nld + n] = make_float2(v00, v01);
                *(float2*)&C[(size_t)(m + 8) * Nld + n] = make_float2(v10, v11);
            }
            if (OUTMODE >= 1) {
                *(unsigned*)&Ch[(size_t)m * Nld + n] = pack_h2(v00, v01);
                *(unsigned*)&Ch[(size_t)(m + 8) * Nld + n] = pack_h2(v10, v11);
            }
        }
    }
}

// ---------------------------------------------------------------------------
// Band-exact top-k + masked softmax.
// S̃ is 1-term fp16 approx (err << BAND). Radix-select τ̃ = 1638th of S̃.
// S̃ > τ̃+BAND: certainly kept; S̃ < τ̃−BAND: certainly dropped; band elements
// resolved by exact fp32 dot(Q[row], K[col]) ranking. Softmax on S̃ values.
// P written as fp16 hi-plane only (PV is 1-term).
// ---------------------------------------------------------------------------
#define BAND 1.5e-3f

__device__ __forceinline__ unsigned f2u(float f) {
    unsigned b = __float_as_uint(f);
    return (b & 0x80000000u) ? ~b : (b | 0x80000000u);
}
__device__ __forceinline__ float u2f(unsigned u) {
    unsigned b = (u & 0x80000000u) ? (u & 0x7fffffffu) : ~u;
    return __uint_as_float(b);
}

__global__ void __launch_bounds__(256) topk_softmax(const float* __restrict__ S,
                                                    const float* __restrict__ Qf,
                                                    const float* __restrict__ Kf,
                                                    __half* __restrict__ Ph) {
    const int row = blockIdx.x;          // [0, BB*NN)
    const int batch = row >> 11;
    const float* p = S + (size_t)row * NN;
    const int tid = threadIdx.x;

    __shared__ float Qs[CC];
    __shared__ int hist[256];
    __shared__ int s_digit, s_rem;
    __shared__ unsigned s_warpk[8];
    __shared__ float s_warpf[8];
    __shared__ float s_sum;
    __shared__ int s_nin, s_bandcnt;
    __shared__ short s_bandidx[64];
    __shared__ float s_bandval[64];
    __shared__ unsigned char s_bandkeep[64];

    // cache Q row (fp32) for band recompute
#pragma unroll
    for (int i = 0; i < CC / 256; i++)
        Qs[tid + i * 256] = Qf[(size_t)row * CC + tid + i * 256];

    // load S̃ row (vectorized)
    float val[8];
    unsigned key[8];
    {
        float4 v0 = *(const float4*)&p[tid * 4];
        float4 v1 = *(const float4*)&p[1024 + tid * 4];
        val[0] = v0.x; val[1] = v0.y; val[2] = v0.z; val[3] = v0.w;
        val[4] = v1.x; val[5] = v1.y; val[6] = v1.z; val[7] = v1.w;
    }
    unsigned lmax = 0;
#pragma unroll
    for (int i = 0; i < 8; i++) {
        key[i] = f2u(val[i]);
        lmax = max(lmax, key[i]);
    }

    lmax = __reduce_max_sync(0xffffffffu, lmax);
    if ((tid & 31) == 0) s_warpk[tid >> 5] = lmax;
    __syncthreads();
    if (tid == 0) {
        unsigned m = s_warpk[0];
#pragma unroll
        for (int w = 1; w < 8; w++) m = max(m, s_warpk[w]);
        s_warpk[0] = m;
        s_rem = KKEEP;
        s_nin = 0;
        s_bandcnt = 0;
    }

    // radix select τ̃ = 1638th largest of S̃ (4 passes, warp-scan)
    unsigned prefix = 0, pmask = 0;
    for (int shift = 24; shift >= 0; shift -= 8) {
        hist[tid] = 0;
        __syncthreads();
#pragma unroll
        for (int i = 0; i < 8; i++)
            if ((key[i] & pmask) == prefix)
                atomicAdd(&hist[(key[i] >> shift) & 255], 1);
        __syncthreads();
        if (tid < 32) {
            const int base = tid * 8;
            int c[8], tot = 0;
#pragma unroll
            for (int j = 0; j < 8; j++) { c[j] = hist[base + j]; tot += c[j]; }
            int incl = tot;
#pragma unroll
            for (int o = 1; o < 32; o <<= 1) {
                int u = __shfl_down_sync(0xffffffffu, incl, o);
                if (tid + o < 32) incl += u;
            }
            const int excl = incl - tot;
            const int remk = s_rem;
            if (excl < remk && excl + tot >= remk) {
                int cum = excl, j = 7;
#pragma unroll
                for (; j > 0; j--) {
                    cum += c[j];
                    if (cum >= remk) break;
                }
                if (cum < remk) cum += c[0];
                s_digit = base + j;
                s_rem = remk - (cum - c[j]);
            }
        }
        __syncthreads();
        prefix |= ((unsigned)s_digit) << shift;
        pmask |= 0xFFu << shift;
    }
    const float tau = u2f(prefix);

    // classify: definitely-in / band / out
    int bandpos[8];
    int ninLocal = 0;
#pragma unroll
    for (int i = 0; i < 8; i++) {
        bandpos[i] = -1;
        if (val[i] > tau + BAND) {
            ninLocal++;
        } else if (val[i] >= tau - BAND) {
            int pos = atomicAdd(&s_bandcnt, 1);
            if (pos < 64) {
                int col = (i < 4) ? (tid * 4 + i) : (1024 + tid * 4 + (i - 4));
                s_bandidx[pos] = (short)col;
                bandpos[i] = pos;
            }
        }
    }
#pragma unroll
    for (int o = 16; o > 0; o >>= 1) ninLocal += __shfl_down_sync(0xffffffffu, ninLocal, o);
    if ((tid & 31) == 0) atomicAdd(&s_nin, ninLocal);
    __syncthreads();

    const int bandcnt = min(s_bandcnt, 64);
    const int need = KKEEP - s_nin;

    // exact fp32 dots for band elements (one warp per element, round-robin)
    {
        const int w = tid >> 5, l = tid & 31;
        for (int b = w; b < bandcnt; b += 8) {
            const float* kr = Kf + ((size_t)(batch * NN + s_bandidx[b])) * CC;
            float sum = 0.f;
#pragma unroll 8
            for (int k = l; k < CC; k += 32) sum += Qs[k] * kr[k];
#pragma unroll
            for (int o = 16; o > 0; o >>= 1) sum += __shfl_down_sync(0xffffffffu, sum, o);
            if (l == 0) s_bandval[b] = sum;
        }
    }
    __syncthreads();

    // rank band by exact value; keep top-'need'
    if (tid < bandcnt) {
        const float v = s_bandval[tid];
        int r = 0;
        for (int j = 0; j < bandcnt; j++) {
            float u = s_bandval[j];
            if (u > v || (u == v && j < tid)) r++;
        }
        s_bandkeep[tid] = (r < need) ? 1 : 0;
    }
    __syncthreads();

    // masked softmax on S̃ values
    const float mval = u2f(s_warpk[0]);
    float e[8];
    float lsum = 0.f;
#pragma unroll
    for (int i = 0; i < 8; i++) {
        bool keep;
        if (val[i] > tau + BAND) keep = true;
        else if (val[i] >= tau - BAND)
            keep = (bandpos[i] >= 0) ? (s_bandkeep[bandpos[i]] != 0) : (val[i] >= tau);
        else keep = false;
        e[i] = keep ? __expf(val[i] - mval) : 0.f;
        lsum += e[i];
    }
#pragma unroll
    for (int o = 16; o > 0; o >>= 1) lsum += __shfl_down_sync(0xffffffffu, lsum, o);
    if ((tid & 31) == 0) s_warpf[tid >> 5] = lsum;
    __syncthreads();
    if (tid == 0) {
        float s = 0.f;
#pragma unroll
        for (int w = 0; w < 8; w++) s += s_warpf[w];
        s_sum = s;
    }
    __syncthreads();
    const float inv = 1.0f / s_sum;

    const size_t ob = (size_t)row * NN + tid * 4;
    *(uint2*)&Ph[ob] = make_uint2(pack_h2(e[0] * inv, e[1] * inv),
                                  pack_h2(e[2] * inv, e[3] * inv));
    *(uint2*)&Ph[ob + 1024] = make_uint2(pack_h2(e[4] * inv, e[5] * inv),
                                         pack_h2(e[6] * inv, e[7] * inv));
}

// ---------------------------------------------------------------------------
// Launch
// ---------------------------------------------------------------------------
extern "C" void kernel_launch(void* const* d_in, const int* in_sizes, int n_in,
                              void* d_out, int out_size) {
    const float* x  = (const float*)d_in[0];
    const float* Wq = (const float*)d_in[1];
    const float* bq = (const float*)d_in[2];
    const float* Wk = (const float*)d_in[3];
    const float* bk = (const float*)d_in[4];
    const float* Wv = (const float*)d_in[5];
    const float* bv = (const float*)d_in[6];
    float* out = (float*)d_out;

    __half *xh, *xl, *Wqh, *Wql, *Wkh, *Wkl, *Wvh;
    __half *Qh, *Kh, *Vh, *Ph;
    float *Qf, *Kf, *S;
    cudaGetSymbolAddress((void**)&xh, g_xh);
    cudaGetSymbolAddress((void**)&xl, g_xl);
    cudaGetSymbolAddress((void**)&Wqh, g_Wqh);
    cudaGetSymbolAddress((void**)&Wql, g_Wql);
    cudaGetSymbolAddress((void**)&Wkh, g_Wkh);
    cudaGetSymbolAddress((void**)&Wkl, g_Wkl);
    cudaGetSymbolAddress((void**)&Wvh, g_Wvh);
    cudaGetSymbolAddress((void**)&Qh, g_Qh);
    cudaGetSymbolAddress((void**)&Kh, g_Kh);
    cudaGetSymbolAddress((void**)&Vh, g_Vh);
    cudaGetSymbolAddress((void**)&Qf, g_Qf);
    cudaGetSymbolAddress((void**)&Kf, g_Kf);
    cudaGetSymbolAddress((void**)&Ph, g_Ph);
    cudaGetSymbolAddress((void**)&S, g_S);

    const int SM3 = 3 * 32768;
    const int SM1 = 3 * 16384;
    cudaFuncSetAttribute(tc_gemm<true, true, 2, 3>,
                         cudaFuncAttributeMaxDynamicSharedMemorySize, SM3);
    cudaFuncSetAttribute(tc_gemm<true, true, 1, 1>,
                         cudaFuncAttributeMaxDynamicSharedMemorySize, SM1);
    cudaFuncSetAttribute(tc_gemm<true, false, 0, 1>,
                         cudaFuncAttributeMaxDynamicSharedMemorySize, SM1);
    cudaFuncSetAttribute(tc_gemm<false, false, 0, 1>,
                         cudaFuncAttributeMaxDynamicSharedMemorySize, SM1);

    // prep: split x (hi+lo); weights: Wq/Wk hi+lo, Wv hi only
    int n4x = BB * NN * CC / 4;
    split_planes<<<n4x / 256, 256>>>(x, xh, xl, n4x);
    int n4w = CC * CC / 4;
    split_planes<<<n4w / 256, 256>>>(Wq, Wqh, Wql, n4w);
    split_planes<<<n4w / 256, 256>>>(Wk, Wkh, Wkl, n4w);
    split_planes<<<n4w / 256, 256>>>(Wv, Wvh, nullptr, n4w);

    dim3 thr(256);

    // Q, K projections: 3-term, output fp32 + hi-plane (feed band-exact topk)
    dim3 gqkv(CC / 128, (BB * NN) / 128, 1);
    tc_gemm<true, true, 2, 3><<<gqkv, thr, SM3>>>(
        xh, xl, Wqh, Wql, Qf, Qh, bq, CC, CC, CC, CC, 0, 0, 0, 1.0f);
    tc_gemm<true, true, 2, 3><<<gqkv, thr, SM3>>>(
        xh, xl, Wkh, Wkl, Kf, Kh, bk, CC, CC, CC, CC, 0, 0, 0, 1.0f);
    // V projection: 1-term (smooth path), hi-plane out
    tc_gemm<true, true, 1, 1><<<gqkv, thr, SM1>>>(
        xh, xh, Wvh, Wvh, nullptr, Vh, bv, CC, CC, CC, CC, 0, 0, 0, 1.0f);

    // S̃ = Qh Kh^T / sqrt(C): 1-term fp16 (band-exact topk resolves boundary)
    dim3 gs(NN / 128, NN / 128, BB);
    tc_gemm<true, false, 0, 1><<<gs, thr, SM1>>>(
        Qh, Qh, Kh, Kh, S, nullptr, nullptr, NN, CC, CC, CC,
        (long long)NN * CC, (long long)NN * CC, (long long)NN * NN, 0.03125f);

    // band-exact top-k + softmax -> P hi-plane
    topk_softmax<<<BB * NN, 256>>>(S, Qf, Kf, Ph);

    // O = P V: 1-term (Ph · Vh)
    dim3 go(CC / 128, NN / 128, BB);
    tc_gemm<false, false, 0, 1><<<go, thr, SM1>>>(
        Ph, Ph, Vh, Vh, out, nullptr, nullptr, CC, NN, CC, NN,
        (long long)NN * NN, (long long)NN * CC, (long long)NN * CC, 1.0f);
}

// round 17
// speedup vs baseline: 2.3226x; 1.0251x over previous
#include <cuda_runtime.h>
#include <cuda_fp16.h>
#include <cstdint>

// Problem constants
#define BB 8
#define NN 2048
#define CC 1024
#define KKEEP 1638

// Scratch (allocation-free rule: __device__ globals)
__device__ __half g_xh[BB * NN * CC], g_xl[BB * NN * CC];
__device__ __half g_Wqh[CC * CC], g_Wql[CC * CC];
__device__ __half g_Wkh[CC * CC], g_Wkl[CC * CC];
__device__ __half g_Wvh[CC * CC];
__device__ __half g_Qh[BB * NN * CC];
__device__ __half g_Kh[BB * NN * CC];
__device__ __half g_Vh[BB * NN * CC];
__device__ float g_Qf[BB * NN * CC];     // fp32 Q for band-exact recompute
__device__ float g_Kf[BB * NN * CC];     // fp32 K
__device__ __half g_S[(size_t)BB * NN * NN];   // S̃ in fp16
__device__ __half g_Ph[(size_t)BB * NN * NN];

// ---------------------------------------------------------------------------
// helpers
// ---------------------------------------------------------------------------
__device__ __forceinline__ void split2(float v0, float v1, unsigned& hi, unsigned& lo) {
    __half2 h = __floats2half2_rn(v0, v1);
    float2 hf = __half22float2(h);
    __half2 l = __floats2half2_rn(v0 - hf.x, v1 - hf.y);
    hi = *reinterpret_cast<unsigned*>(&h);
    lo = *reinterpret_cast<unsigned*>(&l);
}
__device__ __forceinline__ unsigned pack_h2(float v0, float v1) {
    __half2 h = __floats2half2_rn(v0, v1);
    return *reinterpret_cast<unsigned*>(&h);
}

__device__ __forceinline__ void mma16(float* c, const unsigned* a, const unsigned* b) {
    asm volatile(
        "mma.sync.aligned.m16n8k16.row.col.f32.f16.f16.f32 "
        "{%0,%1,%2,%3}, {%4,%5,%6,%7}, {%8,%9}, {%0,%1,%2,%3};"
        : "+f"(c[0]), "+f"(c[1]), "+f"(c[2]), "+f"(c[3])
        : "r"(a[0]), "r"(a[1]), "r"(a[2]), "r"(a[3]), "r"(b[0]), "r"(b[1]));
}
__device__ __forceinline__ void ldm4(unsigned* r, unsigned addr) {
    asm volatile("ldmatrix.sync.aligned.m8n8.x4.shared.b16 {%0,%1,%2,%3}, [%4];"
                 : "=r"(r[0]), "=r"(r[1]), "=r"(r[2]), "=r"(r[3]) : "r"(addr));
}
__device__ __forceinline__ void ldm4t(unsigned* r, unsigned addr) {
    asm volatile("ldmatrix.sync.aligned.m8n8.x4.trans.shared.b16 {%0,%1,%2,%3}, [%4];"
                 : "=r"(r[0]), "=r"(r[1]), "=r"(r[2]), "=r"(r[3]) : "r"(addr));
}
__device__ __forceinline__ void cpa(unsigned s, const void* g) {
    asm volatile("cp.async.cg.shared.global [%0], [%1], 16;" :: "r"(s), "l"(g));
}

// ---------------------------------------------------------------------------
// prep: split fp32 array into fp16 hi/lo planes (lo may be null -> hi only)
// ---------------------------------------------------------------------------
__global__ void split_planes(const float* __restrict__ src,
                             __half* __restrict__ h,
                             __half* __restrict__ l, int n4) {
    int i = blockIdx.x * blockDim.x + threadIdx.x;
    if (i < n4) {
        float4 v = ((const float4*)src)[i];
        unsigned h0, l0, h1, l1;
        split2(v.x, v.y, h0, l0);
        split2(v.z, v.w, h1, l1);
        ((uint2*)h)[i] = make_uint2(h0, h1);
        if (l) ((uint2*)l)[i] = make_uint2(l0, l1);
    }
}

// ---------------------------------------------------------------------------
// GEMM: pre-split fp16 planes; cp.async 3-stage; ldmatrix + mma.
// CTA tile 128x128, K_tile=KT (32 or 64), 256 threads, 8 warps (2x4) of 64x32.
//   TERMS: 3 = ah*bh+ah*bl+al*bh; 2 = ah*bh+al*bh; 1 = ah*bh
//   OUTMODE: 0 = fp32 C; 1 = fp16 hi-plane Ch; 2 = fp32 C AND hi-plane Ch
//   TRANSB: true -> B planes [N][K] (NT); false -> [K][N] (NN, ldmatrix.trans)
// Plane = 256*KT bytes. smem stage: AH [AL] BH [BL].
//   A/NT-B rows: 2*KT bytes, chunk swizzle: KT=32 -> c^((r>>1)&3), KT=64 -> c^(r&7)
//   NN-B rows: 256B, chunk swizzle c ^ (r&7)
// ---------------------------------------------------------------------------
template <bool TRANSB, bool BIAS, int OUTMODE, int TERMS, int KT>
__global__ void __launch_bounds__(256, 2)
tc_gemm(const __half* __restrict__ Ah, const __half* __restrict__ Al,
        const __half* __restrict__ Bh, const __half* __restrict__ Bl,
        float* __restrict__ C, __half* __restrict__ Ch,
        const float* __restrict__ bias,
        int Nld, int lda, int ldb, int K,
        long long sA, long long sB, long long sC, float scale) {
    constexpr unsigned PL = 256u * KT;   // bytes per plane
    constexpr unsigned STG = ((TERMS == 3) ? 4u : (TERMS == 2) ? 3u : 2u) * PL;
    constexpr unsigned BOFF = ((TERMS >= 2) ? 2u : 1u) * PL;
    constexpr int LPT = KT / 16;          // cp.async 16B loads per thread per matrix
    constexpr int CH = KT / 8;            // 16B chunks per A-row
    extern __shared__ __align__(16) unsigned char dsm[];
    const unsigned stiles = (unsigned)__cvta_generic_to_shared(dsm);

    Ah += (size_t)blockIdx.z * sA;
    if (TERMS >= 2) Al += (size_t)blockIdx.z * sA;
    Bh += (size_t)blockIdx.z * sB;
    if (TERMS == 3) Bl += (size_t)blockIdx.z * sB;
    if (OUTMODE != 1) C += (size_t)blockIdx.z * sC;
    if (OUTMODE >= 1) Ch += (size_t)blockIdx.z * sC;

    const int t = threadIdx.x;
    const int lane = t & 31;
    const int warp = t >> 5;
    const int wm = warp & 1;
    const int wn = warp >> 1;
    const int g = lane >> 2;
    const int tg = lane & 3;

    const int m0 = blockIdx.y * 128;
    const int n0 = blockIdx.x * 128;
    const int aBase = wm * 64;
    const int bBase = wn * 32;

    auto aswz = [](int r, int c) -> int {
        return (KT == 32) ? (c ^ ((r >> 1) & 3)) : (c ^ (r & 7));
    };

    float acc[4][4][4];
#pragma unroll
    for (int i = 0; i < 4; i++)
#pragma unroll
        for (int j = 0; j < 4; j++)
#pragma unroll
            for (int r = 0; r < 4; r++) acc[i][j][r] = 0.f;

    const int NK = K / KT;

    // ---- per-thread cp.async src/dst, computed once ----
    unsigned soA[LPT], soB[LPT];
    size_t goA[LPT], goB[LPT];
#pragma unroll
    for (int p = 0; p < LPT; p++) {
        int idx = t + p * 256;
        {
            int r = idx / CH, c = idx % CH;
            soA[p] = (unsigned)(r * (CH * 16) + (aswz(r, c) << 4));
            goA[p] = (size_t)(m0 + r) * lda + c * 8;
        }
        if (TRANSB) {
            int r = idx / CH, c = idx % CH;
            soB[p] = BOFF + (unsigned)(r * (CH * 16) + (aswz(r, c) << 4));
            goB[p] = (size_t)(n0 + r) * ldb + c * 8;
        } else {
            int r = idx >> 4, c = idx & 15;
            soB[p] = BOFF + (unsigned)(r * 256 + ((c ^ (r & 7)) << 4));
            goB[p] = (size_t)r * ldb + n0 + c * 8;
        }
    }

    auto cpa_A = [&](int kt, unsigned off) {
        const size_t kadd = (size_t)kt * KT;
#pragma unroll
        for (int p = 0; p < LPT; p++) {
            cpa(off + soA[p], Ah + goA[p] + kadd);
            if (TERMS >= 2) cpa(off + soA[p] + PL, Al + goA[p] + kadd);
        }
    };
    auto cpa_B = [&](int kt, unsigned off) {
        const size_t kadd = TRANSB ? (size_t)kt * KT : (size_t)kt * KT * ldb;
#pragma unroll
        for (int p = 0; p < LPT; p++) {
            cpa(off + soB[p], Bh + goB[p] + kadd);
            if (TERMS == 3) cpa(off + soB[p] + PL, Bl + goB[p] + kadd);
        }
    };

    // ---- per-thread ldmatrix offsets (relative to stage base) ----
    unsigned axk[4][LPT];
#pragma unroll
    for (int mt = 0; mt < 4; mt++) {
        int ar = aBase + mt * 16 + (lane & 15);
        int c0 = lane >> 4;
#pragma unroll
        for (int ks = 0; ks < LPT; ks++)
            axk[mt][ks] = (unsigned)(ar * (CH * 16) + (aswz(ar, 2 * ks + c0) << 4));
    }
    unsigned bxk[2][LPT];
    if (TRANSB) {
#pragma unroll
        for (int p = 0; p < 2; p++) {
            int br = bBase + p * 16 + (lane & 7) + (lane >> 4) * 8;
            int c0 = (lane >> 3) & 1;
#pragma unroll
            for (int ks = 0; ks < LPT; ks++)
                bxk[p][ks] = BOFF + (unsigned)(br * (CH * 16) + (aswz(br, 2 * ks + c0) << 4));
        }
    } else {
        int kr = (lane & 7) + ((lane >> 3) & 1) * 8;
#pragma unroll
        for (int p = 0; p < 2; p++) {
            int c = bBase / 8 + (lane >> 4) + 2 * p;
            unsigned b0 = BOFF + (unsigned)(kr * 256 + ((c ^ (kr & 7)) << 4));
#pragma unroll
            for (int ks = 0; ks < LPT; ks++) bxk[p][ks] = b0 + (unsigned)ks * 4096u;
        }
    }

    // ---- prologue: stages 0 and 1 ----
    cpa_A(0, stiles);
    cpa_B(0, stiles);
    asm volatile("cp.async.commit_group;" ::: "memory");
    cpa_A(1, stiles + STG);
    cpa_B(1, stiles + STG);
    asm volatile("cp.async.commit_group;" ::: "memory");

    unsigned coff = stiles;                 // compute stage base
    unsigned loff = stiles + 2 * STG;       // load stage base (kt+2)
    const unsigned topoff = stiles + 2 * STG;

    for (int kt = 0; kt < NK; kt++) {
        asm volatile("cp.async.wait_group 1;" ::: "memory");
        __syncthreads();
        const bool more = (kt + 2) < NK;

#pragma unroll
        for (int ks = 0; ks < LPT; ks++) {
            unsigned ah[4][4], bh[2][4], bl[2][4];
#pragma unroll
            for (int mt = 0; mt < 4; mt++) ldm4(ah[mt], coff + axk[mt][ks]);
#pragma unroll
            for (int p = 0; p < 2; p++) {
                if (TRANSB) ldm4(bh[p], coff + bxk[p][ks]);
                else        ldm4t(bh[p], coff + bxk[p][ks]);
            }
            if (TERMS == 3) {
#pragma unroll
                for (int p = 0; p < 2; p++) {
                    if (TRANSB) ldm4(bl[p], coff + bxk[p][ks] + PL);
                    else        ldm4t(bl[p], coff + bxk[p][ks] + PL);
                }
            }
            if (more) { if (ks == 0) cpa_A(kt + 2, loff); else if (ks == 1) cpa_B(kt + 2, loff); }

#pragma unroll
            for (int mt = 0; mt < 4; mt++)
#pragma unroll
                for (int nt = 0; nt < 4; nt++)
                    mma16(acc[mt][nt], ah[mt], &bh[nt >> 1][(nt & 1) * 2]);
            if (TERMS == 3) {
#pragma unroll
                for (int mt = 0; mt < 4; mt++)
#pragma unroll
                    for (int nt = 0; nt < 4; nt++)
                        mma16(acc[mt][nt], ah[mt], &bl[nt >> 1][(nt & 1) * 2]);
            }
            if (TERMS >= 2) {
                unsigned al[4][4];
#pragma unroll
                for (int mt = 0; mt < 4; mt++) ldm4(al[mt], coff + axk[mt][ks] + PL);
#pragma unroll
                for (int mt = 0; mt < 4; mt++)
#pragma unroll
                    for (int nt = 0; nt < 4; nt++)
                        mma16(acc[mt][nt], al[mt], &bh[nt >> 1][(nt & 1) * 2]);
            }
        }

        asm volatile("cp.async.commit_group;" ::: "memory");
        coff = (coff == topoff) ? stiles : coff + STG;
        loff = (loff == topoff) ? stiles : loff + STG;
    }

    // ---- epilogue ----
#pragma unroll
    for (int mt = 0; mt < 4; mt++) {
        int m = m0 + aBase + mt * 16 + g;
#pragma unroll
        for (int nt = 0; nt < 4; nt++) {
            int n = n0 + bBase + nt * 8 + tg * 2;
            float b0 = 0.f, b1 = 0.f;
            if (BIAS) { b0 = bias[n]; b1 = bias[n + 1]; }
            float v00 = acc[mt][nt][0] * scale + b0;
            float v01 = acc[mt][nt][1] * scale + b1;
            float v10 = acc[mt][nt][2] * scale + b0;
            float v11 = acc[mt][nt][3] * scale + b1;
            if (OUTMODE != 1) {
                *(float2*)&C[(size_t)m * Nld + n] = make_float2(v00, v01);
                *(float2*)&C[(size_t)(m + 8) * Nld + n] = make_float2(v10, v11);
            }
            if (OUTMODE >= 1) {
                *(unsigned*)&Ch[(size_t)m * Nld + n] = pack_h2(v00, v01);
                *(unsigned*)&Ch[(size_t)(m + 8) * Nld + n] = pack_h2(v10, v11);
            }
        }
    }
}

// ---------------------------------------------------------------------------
// Band-exact top-k + masked softmax on fp16 S̃.
// 2-pass radix select on sortable 16-bit keys -> τ̃; elements within ±BAND of
// τ̃ get exact fp32 dot(Q,K) ranking; others classified directly.
// ---------------------------------------------------------------------------
#define BAND 1.5e-3f

__device__ __forceinline__ float u2f16(unsigned key) {
    unsigned short b = (key & 0x8000u) ? (unsigned short)(key & 0x7FFFu)
                                       : (unsigned short)(~key);
    __half_raw hr; hr.x = b;
    return __half2float(*(__half*)&hr);
}

__global__ void __launch_bounds__(256) topk_softmax(const __half* __restrict__ S,
                                                    const float* __restrict__ Qf,
                                                    const float* __restrict__ Kf,
                                                    __half* __restrict__ Ph) {
    const int row = blockIdx.x;          // [0, BB*NN)
    const int batch = row >> 11;
    const int tid = threadIdx.x;

    __shared__ float Qs[CC];
    __shared__ int hist[256];
    __shared__ int s_digit, s_rem;
    __shared__ unsigned s_warpk[8];
    __shared__ float s_warpf[8];
    __shared__ float s_sum;
    __shared__ int s_nin, s_bandcnt;
    __shared__ short s_bandidx[64];
    __shared__ float s_bandval[64];
    __shared__ unsigned char s_bandkeep[64];

    // cache Q row (fp32) for band recompute
#pragma unroll
    for (int i = 0; i < CC / 256; i++)
        Qs[tid + i * 256] = Qf[(size_t)row * CC + tid + i * 256];

    // load 8 fp16 values (one uint4 per thread)
    float val[8];
    unsigned key[8];
    {
        uint4 raw = ((const uint4*)(S + (size_t)row * NN))[tid];
        unsigned hw[4] = {raw.x, raw.y, raw.z, raw.w};
#pragma unroll
        for (int i = 0; i < 8; i++) {
            unsigned b = (hw[i >> 1] >> ((i & 1) * 16)) & 0xFFFFu;
            __half_raw hr; hr.x = (unsigned short)b;
            val[i] = __half2float(*(__half*)&hr);
            key[i] = (b & 0x8000u) ? ((~b) & 0xFFFFu) : (b | 0x8000u);
        }
    }
    unsigned lmax = 0;
#pragma unroll
    for (int i = 0; i < 8; i++) lmax = max(lmax, key[i]);

    lmax = __reduce_max_sync(0xffffffffu, lmax);
    if ((tid & 31) == 0) s_warpk[tid >> 5] = lmax;
    __syncthreads();
    if (tid == 0) {
        unsigned m = s_warpk[0];
#pragma unroll
        for (int w = 1; w < 8; w++) m = max(m, s_warpk[w]);
        s_warpk[0] = m;
        s_rem = KKEEP;
        s_nin = 0;
        s_bandcnt = 0;
    }

    // radix select τ̃ = 1638th largest (2 passes over 16-bit keys)
    unsigned prefix = 0, pmask = 0;
#pragma unroll
    for (int shift = 8; shift >= 0; shift -= 8) {
        hist[tid] = 0;
        __syncthreads();
#pragma unroll
        for (int i = 0; i < 8; i++)
            if ((key[i] & pmask) == prefix)
                atomicAdd(&hist[(key[i] >> shift) & 255], 1);
        __syncthreads();
        if (tid < 32) {
            const int base = tid * 8;
            int c[8], tot = 0;
#pragma unroll
            for (int j = 0; j < 8; j++) { c[j] = hist[base + j]; tot += c[j]; }
            int incl = tot;
#pragma unroll
            for (int o = 1; o < 32; o <<= 1) {
                int u = __shfl_down_sync(0xffffffffu, incl, o);
                if (tid + o < 32) incl += u;
            }
            const int excl = incl - tot;
            const int remk = s_rem;
            if (excl < remk && excl + tot >= remk) {
                int cum = excl, j = 7;
#pragma unroll
                for (; j > 0; j--) {
                    cum += c[j];
                    if (cum >= remk) break;
                }
                if (cum < remk) cum += c[0];
                s_digit = base + j;
                s_rem = remk - (cum - c[j]);
            }
        }
        __syncthreads();
        prefix |= ((unsigned)s_digit) << shift;
        pmask |= 0xFFu << shift;
    }
    const float tau = u2f16(prefix);

    // classify: definitely-in / band / out
    int bandpos[8];
    int ninLocal = 0;
#pragma unroll
    for (int i = 0; i < 8; i++) {
        bandpos[i] = -1;
        if (val[i] > tau + BAND) {
            ninLocal++;
        } else if (val[i] >= tau - BAND) {
            int pos = atomicAdd(&s_bandcnt, 1);
            if (pos < 64) {
                s_bandidx[pos] = (short)(tid * 8 + i);
                bandpos[i] = pos;
            }
        }
    }
#pragma unroll
    for (int o = 16; o > 0; o >>= 1) ninLocal += __shfl_down_sync(0xffffffffu, ninLocal, o);
    if ((tid & 31) == 0) atomicAdd(&s_nin, ninLocal);
    __syncthreads();

    const int bandcnt = min(s_bandcnt, 64);
    const int need = KKEEP - s_nin;

    // exact fp32 dots for band elements (one warp per element, round-robin)
    {
        const int w = tid >> 5, l = tid & 31;
        for (int b = w; b < bandcnt; b += 8) {
            const float* kr = Kf + ((size_t)(batch * NN + s_bandidx[b])) * CC;
            float sum = 0.f;
#pragma unroll 8
            for (int k = l; k < CC; k += 32) sum += Qs[k] * kr[k];
#pragma unroll
            for (int o = 16; o > 0; o >>= 1) sum += __shfl_down_sync(0xffffffffu, sum, o);
            if (l == 0) s_bandval[b] = sum;
        }
    }
    __syncthreads();

    // rank band by exact value; keep top-'need'
    if (tid < bandcnt) {
        const float v = s_bandval[tid];
        int r = 0;
        for (int j = 0; j < bandcnt; j++) {
            float u = s_bandval[j];
            if (u > v || (u == v && j < tid)) r++;
        }
        s_bandkeep[tid] = (r < need) ? 1 : 0;
    }
    __syncthreads();

    // masked softmax on S̃ values
    const float mval = u2f16(s_warpk[0]);
    float e[8];
    float lsum = 0.f;
#pragma unroll
    for (int i = 0; i < 8; i++) {
        bool keep;
        if (val[i] > tau + BAND) keep = true;
        else if (val[i] >= tau - BAND)
            keep = (bandpos[i] >= 0) ? (s_bandkeep[bandpos[i]] != 0) : (val[i] >= tau);
        else keep = false;
        e[i] = keep ? __expf(val[i] - mval) : 0.f;
        lsum += e[i];
    }
#pragma unroll
    for (int o = 16; o > 0; o >>= 1) lsum += __shfl_down_sync(0xffffffffu, lsum, o);
    if ((tid & 31) == 0) s_warpf[tid >> 5] = lsum;
    __syncthreads();
    if (tid == 0) {
        float s = 0.f;
#pragma unroll
        for (int w = 0; w < 8; w++) s += s_warpf[w];
        s_sum = s;
    }
    __syncthreads();
    const float inv = 1.0f / s_sum;

    uint4 outv;
    outv.x = pack_h2(e[0] * inv, e[1] * inv);
    outv.y = pack_h2(e[2] * inv, e[3] * inv);
    outv.z = pack_h2(e[4] * inv, e[5] * inv);
    outv.w = pack_h2(e[6] * inv, e[7] * inv);
    ((uint4*)(Ph + (size_t)row * NN))[tid] = outv;
}

// ---------------------------------------------------------------------------
// Launch
// ---------------------------------------------------------------------------
extern "C" void kernel_launch(void* const* d_in, const int* in_sizes, int n_in,
                              void* d_out, int out_size) {
    const float* x  = (const float*)d_in[0];
    const float* Wq = (const float*)d_in[1];
    const float* bq = (const float*)d_in[2];
    const float* Wk = (const float*)d_in[3];
    const float* bk = (const float*)d_in[4];
    const float* Wv = (const float*)d_in[5];
    const float* bv = (const float*)d_in[6];
    float* out = (float*)d_out;

    __half *xh, *xl, *Wqh, *Wql, *Wkh, *Wkl, *Wvh;
    __half *Qh, *Kh, *Vh, *Ph, *S;
    float *Qf, *Kf;
    cudaGetSymbolAddress((void**)&xh, g_xh);
    cudaGetSymbolAddress((void**)&xl, g_xl);
    cudaGetSymbolAddress((void**)&Wqh, g_Wqh);
    cudaGetSymbolAddress((void**)&Wql, g_Wql);
    cudaGetSymbolAddress((void**)&Wkh, g_Wkh);
    cudaGetSymbolAddress((void**)&Wkl, g_Wkl);
    cudaGetSymbolAddress((void**)&Wvh, g_Wvh);
    cudaGetSymbolAddress((void**)&Qh, g_Qh);
    cudaGetSymbolAddress((void**)&Kh, g_Kh);
    cudaGetSymbolAddress((void**)&Vh, g_Vh);
    cudaGetSymbolAddress((void**)&Qf, g_Qf);
    cudaGetSymbolAddress((void**)&Kf, g_Kf);
    cudaGetSymbolAddress((void**)&Ph, g_Ph);
    cudaGetSymbolAddress((void**)&S, g_S);

    const int SM3 = 3 * 32768;    // 3-term, KT=32
    const int SM1 = 3 * 32768;    // 1-term, KT=64 (2 planes x 16KB x 3 stages)
    cudaFuncSetAttribute(tc_gemm<true, true, 2, 3, 32>,
                         cudaFuncAttributeMaxDynamicSharedMemorySize, SM3);
    cudaFuncSetAttribute(tc_gemm<true, true, 1, 1, 64>,
                         cudaFuncAttributeMaxDynamicSharedMemorySize, SM1);
    cudaFuncSetAttribute(tc_gemm<true, false, 1, 1, 64>,
                         cudaFuncAttributeMaxDynamicSharedMemorySize, SM1);
    cudaFuncSetAttribute(tc_gemm<false, false, 0, 1, 64>,
                         cudaFuncAttributeMaxDynamicSharedMemorySize, SM1);

    // prep: split x (hi+lo); weights: Wq/Wk hi+lo, Wv hi only
    int n4x = BB * NN * CC / 4;
    split_planes<<<n4x / 256, 256>>>(x, xh, xl, n4x);
    int n4w = CC * CC / 4;
    split_planes<<<n4w / 256, 256>>>(Wq, Wqh, Wql, n4w);
    split_planes<<<n4w / 256, 256>>>(Wk, Wkh, Wkl, n4w);
    split_planes<<<n4w / 256, 256>>>(Wv, Wvh, nullptr, n4w);

    dim3 thr(256);

    // Q, K projections: 3-term, output fp32 + hi-plane (feed band-exact topk)
    dim3 gqkv(CC / 128, (BB * NN) / 128, 1);
    tc_gemm<true, true, 2, 3, 32><<<gqkv, thr, SM3>>>(
        xh, xl, Wqh, Wql, Qf, Qh, bq, CC, CC, CC, CC, 0, 0, 0, 1.0f);
    tc_gemm<true, true, 2, 3, 32><<<gqkv, thr, SM3>>>(
        xh, xl, Wkh, Wkl, Kf, Kh, bk, CC, CC, CC, CC, 0, 0, 0, 1.0f);
    // V projection: 1-term, KT=64, hi-plane out
    tc_gemm<true, true, 1, 1, 64><<<gqkv, thr, SM1>>>(
        xh, xh, Wvh, Wvh, nullptr, Vh, bv, CC, CC, CC, CC, 0, 0, 0, 1.0f);

    // S̃ = Qh Kh^T / sqrt(C): 1-term, KT=64, fp16 out
    dim3 gs(NN / 128, NN / 128, BB);
    tc_gemm<true, false, 1, 1, 64><<<gs, thr, SM1>>>(
        Qh, Qh, Kh, Kh, nullptr, S, nullptr, NN, CC, CC, CC,
        (long long)NN * CC, (long long)NN * CC, (long long)NN * NN, 0.03125f);

    // band-exact top-k + softmax -> P hi-plane
    topk_softmax<<<BB * NN, 256>>>(S, Qf, Kf, Ph);

    // O = P V: 1-term, KT=64 (Ph · Vh)
    dim3 go(CC / 128, NN / 128, BB);
    tc_gemm<false, false, 0, 1, 64><<<go, thr, SM1>>>(
        Ph, Ph, Vh, Vh, out, nullptr, nullptr, CC, NN, CC, NN,
        (long long)NN * NN, (long long)NN * CC, (long long)NN * CC, 1.0f);
}